// round 1
// baseline (speedup 1.0000x reference)
#include <cuda_runtime.h>
#include <math.h>

#define S 1024
#define E 1024
#define H 16
#define HD 64
#define BATCH 2
#define BH (BATCH * H)   // 32

// ---------------- scratch (device globals; no runtime allocation) ----------
__device__ float g_q[BH * S * HD];            // 8 MB  [bh][s][d]
__device__ float g_k[BH * S * HD];            // 8 MB
__device__ float g_v[BH * S * HD];            // 8 MB
__device__ float g_logits[BH * S * S];        // 128 MB [bh][q][k]
__device__ float g_attn[BH * S * S];          // 128 MB
__device__ float g_attout[BATCH * S * E];     // 8 MB  [b*S+s][e]
__device__ float g_vsum[BH * HD];

// ============================================================================
// Kernel 1: fused QKV projections.  out = X @ W + b, scattered to [bh][s][d].
// 128x128 tile, BK=8, 256 threads, 8x8 per thread.
// ============================================================================
__global__ __launch_bounds__(256) void proj_qkv_kernel(
    const float* __restrict__ Xq, const float* __restrict__ Xk, const float* __restrict__ Xv,
    const float* __restrict__ Wq, const float* __restrict__ Wk, const float* __restrict__ Wv,
    const float* __restrict__ bq, const float* __restrict__ bk, const float* __restrict__ bv)
{
    const float* X; const float* W; const float* bias; float* out;
    if (blockIdx.z == 0)      { X = Xq; W = Wq; bias = bq; out = g_q; }
    else if (blockIdx.z == 1) { X = Xk; W = Wk; bias = bk; out = g_k; }
    else                      { X = Xv; W = Wv; bias = bv; out = g_v; }

    __shared__ float As[8][128];
    __shared__ float Bs[8][128];

    const int tid  = threadIdx.x;
    const int row0 = blockIdx.y * 128;
    const int col0 = blockIdx.x * 128;
    const int tx = tid & 15, ty = tid >> 4;
    const int aRow = tid >> 1,  aCol = (tid & 1) * 4;
    const int bRow = tid >> 5,  bCol = (tid & 31) * 4;

    float acc[8][8];
#pragma unroll
    for (int i = 0; i < 8; i++)
#pragma unroll
        for (int j = 0; j < 8; j++) acc[i][j] = 0.f;

    const float* Aptr = X + (row0 + aRow) * E + aCol;
    const float* Bptr = W + bRow * E + col0 + bCol;

    for (int k0 = 0; k0 < E; k0 += 8) {
        float4 a = *(const float4*)(Aptr + k0);
        As[aCol + 0][aRow] = a.x; As[aCol + 1][aRow] = a.y;
        As[aCol + 2][aRow] = a.z; As[aCol + 3][aRow] = a.w;
        *(float4*)&Bs[bRow][bCol] = *(const float4*)(Bptr + k0 * E);
        __syncthreads();
#pragma unroll
        for (int kk = 0; kk < 8; kk++) {
            float4 a0 = *(const float4*)&As[kk][ty * 8];
            float4 a1 = *(const float4*)&As[kk][ty * 8 + 4];
            float4 b0 = *(const float4*)&Bs[kk][tx * 8];
            float4 b1 = *(const float4*)&Bs[kk][tx * 8 + 4];
            float ar[8] = {a0.x, a0.y, a0.z, a0.w, a1.x, a1.y, a1.z, a1.w};
            float br[8] = {b0.x, b0.y, b0.z, b0.w, b1.x, b1.y, b1.z, b1.w};
#pragma unroll
            for (int i = 0; i < 8; i++)
#pragma unroll
                for (int j = 0; j < 8; j++) acc[i][j] += ar[i] * br[j];
        }
        __syncthreads();
    }

#pragma unroll
    for (int i = 0; i < 8; i++) {
        int m = row0 + ty * 8 + i;
        int b = m >> 10, s = m & 1023;
#pragma unroll
        for (int j = 0; j < 8; j++) {
            int n = col0 + tx * 8 + j;
            int h = n >> 6, d = n & 63;
            out[b * (H * S * HD) + h * (S * HD) + s * HD + d] = acc[i][j] + bias[n];
        }
    }
}

// ============================================================================
// Kernel 2: logits[bh][q][k] = (q . k) * HD^-0.5, multiplied by causal mask.
// ============================================================================
__global__ __launch_bounds__(256) void logits_kernel()
{
    const int bh   = blockIdx.z;
    const int row0 = blockIdx.y * 128;   // q
    const int col0 = blockIdx.x * 128;   // k
    float* L = g_logits + bh * (S * S);
    const int tid = threadIdx.x;

    if (col0 >= row0 + 128) {  // tile entirely above diagonal -> zeros
        float4 z = make_float4(0.f, 0.f, 0.f, 0.f);
        for (int t = tid; t < 4096; t += 256) {
            int r = t >> 5, c = (t & 31) * 4;
            *(float4*)&L[(row0 + r) * S + col0 + c] = z;
        }
        return;
    }

    const float* qp = g_q + bh * (S * HD);
    const float* kp = g_k + bh * (S * HD);

    __shared__ float As[8][128];
    __shared__ float Bs[8][128];
    const int tx = tid & 15, ty = tid >> 4;
    const int lRow = tid >> 1, lCol = (tid & 1) * 4;

    float acc[8][8];
#pragma unroll
    for (int i = 0; i < 8; i++)
#pragma unroll
        for (int j = 0; j < 8; j++) acc[i][j] = 0.f;

    for (int d0 = 0; d0 < HD; d0 += 8) {
        float4 a = *(const float4*)&qp[(row0 + lRow) * HD + d0 + lCol];
        As[lCol + 0][lRow] = a.x; As[lCol + 1][lRow] = a.y;
        As[lCol + 2][lRow] = a.z; As[lCol + 3][lRow] = a.w;
        float4 b = *(const float4*)&kp[(col0 + lRow) * HD + d0 + lCol];
        Bs[lCol + 0][lRow] = b.x; Bs[lCol + 1][lRow] = b.y;
        Bs[lCol + 2][lRow] = b.z; Bs[lCol + 3][lRow] = b.w;
        __syncthreads();
#pragma unroll
        for (int kk = 0; kk < 8; kk++) {
            float4 a0 = *(const float4*)&As[kk][ty * 8];
            float4 a1 = *(const float4*)&As[kk][ty * 8 + 4];
            float4 b0 = *(const float4*)&Bs[kk][tx * 8];
            float4 b1 = *(const float4*)&Bs[kk][tx * 8 + 4];
            float ar[8] = {a0.x, a0.y, a0.z, a0.w, a1.x, a1.y, a1.z, a1.w};
            float br[8] = {b0.x, b0.y, b0.z, b0.w, b1.x, b1.y, b1.z, b1.w};
#pragma unroll
            for (int i = 0; i < 8; i++)
#pragma unroll
                for (int j = 0; j < 8; j++) acc[i][j] += ar[i] * br[j];
        }
        __syncthreads();
    }

    const float scale = 0.125f;  // 64^-0.5
#pragma unroll
    for (int i = 0; i < 8; i++) {
        int m = row0 + ty * 8 + i;
#pragma unroll
        for (int j = 0; j < 8; j++) {
            int n = col0 + tx * 8 + j;
            L[m * S + n] = (n <= m) ? acc[i][j] * scale : 0.f;
        }
    }
}

// ============================================================================
// Kernel 3: depthwise 3x3 conv over (q,k) with pad (2,2)/(1,1) then row slice,
// + kq_b bias, + softmax over k.  One block handles 8 output rows of one head.
// ============================================================================
__device__ __forceinline__ float block_reduce_max(float v) {
    __shared__ float sm[8];
    int lane = threadIdx.x & 31, wid = threadIdx.x >> 5;
#pragma unroll
    for (int o = 16; o; o >>= 1) v = fmaxf(v, __shfl_xor_sync(0xffffffffu, v, o));
    if (lane == 0) sm[wid] = v;
    __syncthreads();
    if (wid == 0) {
        v = sm[lane & 7];
#pragma unroll
        for (int o = 4; o; o >>= 1) v = fmaxf(v, __shfl_xor_sync(0xffffffffu, v, o));
        if (lane == 0) sm[0] = v;
    }
    __syncthreads();
    v = sm[0];
    __syncthreads();
    return v;
}

__device__ __forceinline__ float block_reduce_sum(float v) {
    __shared__ float ss[8];
    int lane = threadIdx.x & 31, wid = threadIdx.x >> 5;
#pragma unroll
    for (int o = 16; o; o >>= 1) v += __shfl_xor_sync(0xffffffffu, v, o);
    if (lane == 0) ss[wid] = v;
    __syncthreads();
    if (wid == 0) {
        v = ss[lane & 7];
#pragma unroll
        for (int o = 4; o; o >>= 1) v += __shfl_xor_sync(0xffffffffu, v, o);
        if (lane == 0) ss[0] = v;
    }
    __syncthreads();
    v = ss[0];
    __syncthreads();
    return v;
}

#define QROWS 8
__global__ __launch_bounds__(256) void conv_softmax_kernel(
    const float* __restrict__ kq_w, const float* __restrict__ kq_b)
{
    const int bh = blockIdx.y;
    const int h  = bh & 15;
    const int q0 = blockIdx.x * QROWS;
    const float* L = g_logits + bh * (S * S);
    float* A = g_attn + bh * (S * S);

    __shared__ float rows[QROWS + 2][S + 2];
    const int tid = threadIdx.x;
    const int c = tid * 4;

#pragma unroll
    for (int r = 0; r < QROWS + 2; r++) {
        int q = q0 - 2 + r;
        float4 val = make_float4(0.f, 0.f, 0.f, 0.f);
        if (q >= 0) val = *(const float4*)&L[q * S + c];
        rows[r][c + 1] = val.x; rows[r][c + 2] = val.y;
        rows[r][c + 3] = val.z; rows[r][c + 4] = val.w;
        if (tid == 0) rows[r][0] = 0.f;
        if (tid == 1) rows[r][S + 1] = 0.f;
    }

    float wv[9];
#pragma unroll
    for (int t = 0; t < 9; t++) wv[t] = kq_w[h * 9 + t];
    const float bias = kq_b[h];
    __syncthreads();

    for (int i = 0; i < QROWS; i++) {
        const int q = q0 + i;
        float cv[4];
#pragma unroll
        for (int u = 0; u < 4; u++) {
            int k = c + u;
            const float* r0 = &rows[i][k];
            const float* r1 = &rows[i + 1][k];
            const float* r2 = &rows[i + 2][k];
            cv[u] = wv[0] * r0[0] + wv[1] * r0[1] + wv[2] * r0[2]
                  + wv[3] * r1[0] + wv[4] * r1[1] + wv[5] * r1[2]
                  + wv[6] * r2[0] + wv[7] * r2[1] + wv[8] * r2[2] + bias;
        }
        float mx = fmaxf(fmaxf(cv[0], cv[1]), fmaxf(cv[2], cv[3]));
        mx = block_reduce_max(mx);
        float e0 = __expf(cv[0] - mx), e1 = __expf(cv[1] - mx);
        float e2 = __expf(cv[2] - mx), e3 = __expf(cv[3] - mx);
        float sum = block_reduce_sum(e0 + e1 + e2 + e3);
        float inv = 1.f / sum;
        float4 o = make_float4(e0 * inv, e1 * inv, e2 * inv, e3 * inv);
        *(float4*)&A[q * S + c] = o;
    }
}

// ============================================================================
// Kernel 4: column sums of V per head (for the mix_b rank-1 term).
// ============================================================================
__global__ void vsum_kernel()
{
    const int bh = blockIdx.x;
    const int d  = threadIdx.x;
    const float* V = g_v + bh * (S * HD);
    float s = 0.f;
#pragma unroll 8
    for (int t = 0; t < S; t++) s += V[t * HD + d];
    g_vsum[bh * HD + d] = s;
}

// ============================================================================
// Kernel 5: fused head-mix + attn@V + DyT.
//   mixed = m0*attn[h0] + m1*attn[h1]; out = mixed@V + mix_b * colsum(V);
//   out = tanh(alpha*out)*dyt_w + dyt_b; *= depth_scale.
// Tile: 64 q-rows x 64 d-cols, BK=16, 256 threads, 4x4 per thread.
// ============================================================================
__global__ __launch_bounds__(256) void pv_kernel(
    const float* __restrict__ mix_w, const float* __restrict__ mix_b,
    const float* __restrict__ dyt_alpha, const float* __restrict__ dyt_w,
    const float* __restrict__ dyt_b, const float* __restrict__ depth_scale)
{
    const int bh = blockIdx.z;
    const int b = bh >> 4, h = bh & 15;
    const int q0 = blockIdx.y * 64;
    const int h0 = h & ~1;
    const float* A0 = g_attn + (b * 16 + h0) * (S * S);
    const float* A1 = A0 + (S * S);
    const float* V  = g_v + bh * (S * HD);
    const float* vs = g_vsum + bh * HD;
    const float m0 = mix_w[h * 2 + 0], m1 = mix_w[h * 2 + 1];
    const float mb = mix_b[h];
    const float alpha = dyt_alpha[0], ds = depth_scale[0];

    __shared__ float As[16][64];
    __shared__ float Bs[16][64];
    const int tid = threadIdx.x;
    const int ar = tid >> 2,  ac = (tid & 3) * 4;
    const int br = tid >> 4,  bc = (tid & 15) * 4;
    const int tx = tid & 15,  ty = tid >> 4;

    float acc[4][4];
#pragma unroll
    for (int i = 0; i < 4; i++)
#pragma unroll
        for (int j = 0; j < 4; j++) acc[i][j] = 0.f;

    for (int k0 = 0; k0 < S; k0 += 16) {
        float4 a0 = *(const float4*)&A0[(q0 + ar) * S + k0 + ac];
        float4 a1 = *(const float4*)&A1[(q0 + ar) * S + k0 + ac];
        As[ac + 0][ar] = m0 * a0.x + m1 * a1.x;
        As[ac + 1][ar] = m0 * a0.y + m1 * a1.y;
        As[ac + 2][ar] = m0 * a0.z + m1 * a1.z;
        As[ac + 3][ar] = m0 * a0.w + m1 * a1.w;
        *(float4*)&Bs[br][bc] = *(const float4*)&V[(k0 + br) * HD + bc];
        __syncthreads();
#pragma unroll
        for (int kk = 0; kk < 16; kk++) {
            float4 av = *(const float4*)&As[kk][ty * 4];
            float4 bv = *(const float4*)&Bs[kk][tx * 4];
            float arr[4] = {av.x, av.y, av.z, av.w};
            float brr[4] = {bv.x, bv.y, bv.z, bv.w};
#pragma unroll
            for (int i = 0; i < 4; i++)
#pragma unroll
                for (int j = 0; j < 4; j++) acc[i][j] += arr[i] * brr[j];
        }
        __syncthreads();
    }

    float* O = g_attout + (b * S) * E + h * HD;
#pragma unroll
    for (int i = 0; i < 4; i++) {
        int q = q0 + ty * 4 + i;
#pragma unroll
        for (int j = 0; j < 4; j++) {
            int d = tx * 4 + j;
            float v = acc[i][j] + mb * vs[d];
            v = tanhf(alpha * v) * dyt_w[d] + dyt_b[d];
            v *= ds;
            O[q * E + d] = v;
        }
    }
}

// ============================================================================
// Kernel 6: output projection  d_out = attout @ Wo + bo   (plain layout)
// ============================================================================
__global__ __launch_bounds__(256) void out_proj_kernel(
    const float* __restrict__ Wo, const float* __restrict__ bo,
    float* __restrict__ out)
{
    __shared__ float As[8][128];
    __shared__ float Bs[8][128];

    const int tid  = threadIdx.x;
    const int row0 = blockIdx.y * 128;
    const int col0 = blockIdx.x * 128;
    const int tx = tid & 15, ty = tid >> 4;
    const int aRow = tid >> 1,  aCol = (tid & 1) * 4;
    const int bRow = tid >> 5,  bCol = (tid & 31) * 4;

    float acc[8][8];
#pragma unroll
    for (int i = 0; i < 8; i++)
#pragma unroll
        for (int j = 0; j < 8; j++) acc[i][j] = 0.f;

    const float* Aptr = g_attout + (row0 + aRow) * E + aCol;
    const float* Bptr = Wo + bRow * E + col0 + bCol;

    for (int k0 = 0; k0 < E; k0 += 8) {
        float4 a = *(const float4*)(Aptr + k0);
        As[aCol + 0][aRow] = a.x; As[aCol + 1][aRow] = a.y;
        As[aCol + 2][aRow] = a.z; As[aCol + 3][aRow] = a.w;
        *(float4*)&Bs[bRow][bCol] = *(const float4*)(Bptr + k0 * E);
        __syncthreads();
#pragma unroll
        for (int kk = 0; kk < 8; kk++) {
            float4 a0 = *(const float4*)&As[kk][ty * 8];
            float4 a1 = *(const float4*)&As[kk][ty * 8 + 4];
            float4 b0 = *(const float4*)&Bs[kk][tx * 8];
            float4 b1 = *(const float4*)&Bs[kk][tx * 8 + 4];
            float ar[8] = {a0.x, a0.y, a0.z, a0.w, a1.x, a1.y, a1.z, a1.w};
            float br[8] = {b0.x, b0.y, b0.z, b0.w, b1.x, b1.y, b1.z, b1.w};
#pragma unroll
            for (int i = 0; i < 8; i++)
#pragma unroll
                for (int j = 0; j < 8; j++) acc[i][j] += ar[i] * br[j];
        }
        __syncthreads();
    }

#pragma unroll
    for (int i = 0; i < 8; i++) {
        int m = row0 + ty * 8 + i;
#pragma unroll
        for (int j = 0; j < 8; j++) {
            int n = col0 + tx * 8 + j;
            out[m * E + n] = acc[i][j] + bo[n];
        }
    }
}

// ============================================================================
// Launch
// ============================================================================
extern "C" void kernel_launch(void* const* d_in, const int* in_sizes, int n_in,
                              void* d_out, int out_size)
{
    const float* Q   = (const float*)d_in[0];
    const float* K   = (const float*)d_in[1];
    const float* V   = (const float*)d_in[2];
    const float* Wq  = (const float*)d_in[3];
    const float* bq  = (const float*)d_in[4];
    const float* Wk  = (const float*)d_in[5];
    const float* bk  = (const float*)d_in[6];
    const float* Wv  = (const float*)d_in[7];
    const float* bv  = (const float*)d_in[8];
    const float* Wo  = (const float*)d_in[9];
    const float* bo  = (const float*)d_in[10];
    const float* kq_w = (const float*)d_in[11];
    const float* kq_b = (const float*)d_in[12];
    const float* mix_w = (const float*)d_in[13];
    const float* mix_b = (const float*)d_in[14];
    const float* dyt_alpha = (const float*)d_in[15];
    const float* dyt_w = (const float*)d_in[16];
    const float* dyt_b = (const float*)d_in[17];
    const float* depth_scale = (const float*)d_in[18];

    proj_qkv_kernel<<<dim3(8, 16, 3), 256>>>(Q, K, V, Wq, Wk, Wv, bq, bk, bv);
    logits_kernel<<<dim3(8, 8, BH), 256>>>();
    conv_softmax_kernel<<<dim3(S / QROWS, BH), 256>>>(kq_w, kq_b);
    vsum_kernel<<<BH, HD>>>();
    pv_kernel<<<dim3(1, S / 64, BH), 256>>>(mix_w, mix_b, dyt_alpha, dyt_w, dyt_b, depth_scale);
    out_proj_kernel<<<dim3(8, 16), 256>>>(Wo, bo, (float*)d_out);
}

// round 2
// speedup vs baseline: 1.1046x; 1.1046x over previous
#include <cuda_runtime.h>
#include <math.h>

#define S 1024
#define E 1024
#define H 16
#define HD 64
#define BATCH 2
#define BH (BATCH * H)   // 32

// ---------------- scratch (device globals; no runtime allocation) ----------
__device__ float g_q[BH * S * HD];            // 8 MB  [bh][s][d]
__device__ float g_k[BH * S * HD];            // 8 MB
__device__ float g_v[BH * S * HD];            // 8 MB
__device__ float g_logits[BH * S * S];        // 128 MB [bh][q][k] (lower tri valid)
__device__ float g_attn[BH * S * S];          // 128 MB (cols [0,Klim(q)) valid)
__device__ float g_rowconst[BH * S];          // per-row constant attn value
__device__ float g_suffV[BH * 17 * HD];       // V suffix sums at 64-row chunk bounds
__device__ float g_attout[BATCH * S * E];     // 8 MB  [b*S+s][e]

// ============================================================================
// Kernel 1: fused QKV projections.  out = X @ W + b, scattered to [bh][s][d].
// ============================================================================
__global__ __launch_bounds__(256) void proj_qkv_kernel(
    const float* __restrict__ Xq, const float* __restrict__ Xk, const float* __restrict__ Xv,
    const float* __restrict__ Wq, const float* __restrict__ Wk, const float* __restrict__ Wv,
    const float* __restrict__ bq, const float* __restrict__ bk, const float* __restrict__ bv)
{
    const float* X; const float* W; const float* bias; float* out;
    if (blockIdx.z == 0)      { X = Xq; W = Wq; bias = bq; out = g_q; }
    else if (blockIdx.z == 1) { X = Xk; W = Wk; bias = bk; out = g_k; }
    else                      { X = Xv; W = Wv; bias = bv; out = g_v; }

    __shared__ float As[8][128];
    __shared__ float Bs[8][128];

    const int tid  = threadIdx.x;
    const int row0 = blockIdx.y * 128;
    const int col0 = blockIdx.x * 128;
    const int tx = tid & 15, ty = tid >> 4;
    const int aRow = tid >> 1,  aCol = (tid & 1) * 4;
    const int bRow = tid >> 5,  bCol = (tid & 31) * 4;

    float acc[8][8];
#pragma unroll
    for (int i = 0; i < 8; i++)
#pragma unroll
        for (int j = 0; j < 8; j++) acc[i][j] = 0.f;

    const float* Aptr = X + (row0 + aRow) * E + aCol;
    const float* Bptr = W + bRow * E + col0 + bCol;

    for (int k0 = 0; k0 < E; k0 += 8) {
        float4 a = *(const float4*)(Aptr + k0);
        As[aCol + 0][aRow] = a.x; As[aCol + 1][aRow] = a.y;
        As[aCol + 2][aRow] = a.z; As[aCol + 3][aRow] = a.w;
        *(float4*)&Bs[bRow][bCol] = *(const float4*)(Bptr + k0 * E);
        __syncthreads();
#pragma unroll
        for (int kk = 0; kk < 8; kk++) {
            float4 a0 = *(const float4*)&As[kk][ty * 8];
            float4 a1 = *(const float4*)&As[kk][ty * 8 + 4];
            float4 b0 = *(const float4*)&Bs[kk][tx * 8];
            float4 b1 = *(const float4*)&Bs[kk][tx * 8 + 4];
            float ar[8] = {a0.x, a0.y, a0.z, a0.w, a1.x, a1.y, a1.z, a1.w};
            float br[8] = {b0.x, b0.y, b0.z, b0.w, b1.x, b1.y, b1.z, b1.w};
#pragma unroll
            for (int i = 0; i < 8; i++)
#pragma unroll
                for (int j = 0; j < 8; j++) acc[i][j] += ar[i] * br[j];
        }
        __syncthreads();
    }

#pragma unroll
    for (int i = 0; i < 8; i++) {
        int m = row0 + ty * 8 + i;
        int b = m >> 10, s = m & 1023;
#pragma unroll
        for (int j = 0; j < 8; j++) {
            int n = col0 + tx * 8 + j;
            int h = n >> 6, d = n & 63;
            out[b * (H * S * HD) + h * (S * HD) + s * HD + d] = acc[i][j] + bias[n];
        }
    }
}

// ============================================================================
// Kernel 2: logits (lower-triangular tiles only).
// ============================================================================
__global__ __launch_bounds__(256) void logits_kernel()
{
    const int bh = blockIdx.y;
    // map triangular tile index -> (r, c), c <= r, r in 0..7
    int t = blockIdx.x, r = 0;
    while (t > r) { t -= r + 1; r++; }
    const int row0 = r * 128;
    const int col0 = t * 128;

    float* L = g_logits + bh * (S * S);
    const float* qp = g_q + bh * (S * HD);
    const float* kp = g_k + bh * (S * HD);

    __shared__ float As[8][128];
    __shared__ float Bs[8][128];
    const int tid = threadIdx.x;
    const int tx = tid & 15, ty = tid >> 4;
    const int lRow = tid >> 1, lCol = (tid & 1) * 4;

    float acc[8][8];
#pragma unroll
    for (int i = 0; i < 8; i++)
#pragma unroll
        for (int j = 0; j < 8; j++) acc[i][j] = 0.f;

    for (int d0 = 0; d0 < HD; d0 += 8) {
        float4 a = *(const float4*)&qp[(row0 + lRow) * HD + d0 + lCol];
        As[lCol + 0][lRow] = a.x; As[lCol + 1][lRow] = a.y;
        As[lCol + 2][lRow] = a.z; As[lCol + 3][lRow] = a.w;
        float4 b = *(const float4*)&kp[(col0 + lRow) * HD + d0 + lCol];
        Bs[lCol + 0][lRow] = b.x; Bs[lCol + 1][lRow] = b.y;
        Bs[lCol + 2][lRow] = b.z; Bs[lCol + 3][lRow] = b.w;
        __syncthreads();
#pragma unroll
        for (int kk = 0; kk < 8; kk++) {
            float4 a0 = *(const float4*)&As[kk][ty * 8];
            float4 a1 = *(const float4*)&As[kk][ty * 8 + 4];
            float4 b0 = *(const float4*)&Bs[kk][tx * 8];
            float4 b1 = *(const float4*)&Bs[kk][tx * 8 + 4];
            float ar[8] = {a0.x, a0.y, a0.z, a0.w, a1.x, a1.y, a1.z, a1.w};
            float br[8] = {b0.x, b0.y, b0.z, b0.w, b1.x, b1.y, b1.z, b1.w};
#pragma unroll
            for (int i = 0; i < 8; i++)
#pragma unroll
                for (int j = 0; j < 8; j++) acc[i][j] += ar[i] * br[j];
        }
        __syncthreads();
    }

    const float scale = 0.125f;  // 64^-0.5
#pragma unroll
    for (int i = 0; i < 8; i++) {
        int m = row0 + ty * 8 + i;
#pragma unroll
        for (int j = 0; j < 8; j++) {
            int n = col0 + tx * 8 + j;
            L[m * S + n] = (n <= m) ? acc[i][j] * scale : 0.f;
        }
    }
}

// ============================================================================
// Kernel 3: conv (k <= q+1 only) + analytic-constant softmax.
// ============================================================================
__device__ __forceinline__ float block_reduce_max(float v) {
    __shared__ float sm[8];
    int lane = threadIdx.x & 31, wid = threadIdx.x >> 5;
#pragma unroll
    for (int o = 16; o; o >>= 1) v = fmaxf(v, __shfl_xor_sync(0xffffffffu, v, o));
    if (lane == 0) sm[wid] = v;
    __syncthreads();
    if (wid == 0) {
        v = sm[lane & 7];
#pragma unroll
        for (int o = 4; o; o >>= 1) v = fmaxf(v, __shfl_xor_sync(0xffffffffu, v, o));
        if (lane == 0) sm[0] = v;
    }
    __syncthreads();
    v = sm[0];
    __syncthreads();
    return v;
}

__device__ __forceinline__ float block_reduce_sum(float v) {
    __shared__ float ss[8];
    int lane = threadIdx.x & 31, wid = threadIdx.x >> 5;
#pragma unroll
    for (int o = 16; o; o >>= 1) v += __shfl_xor_sync(0xffffffffu, v, o);
    if (lane == 0) ss[wid] = v;
    __syncthreads();
    if (wid == 0) {
        v = ss[lane & 7];
#pragma unroll
        for (int o = 4; o; o >>= 1) v += __shfl_xor_sync(0xffffffffu, v, o);
        if (lane == 0) ss[0] = v;
    }
    __syncthreads();
    v = ss[0];
    __syncthreads();
    return v;
}

#define QROWS 8
__global__ __launch_bounds__(256) void conv_softmax_kernel(
    const float* __restrict__ kq_w, const float* __restrict__ kq_b)
{
    const int bh = blockIdx.y;
    const int h  = bh & 15;
    const int q0 = blockIdx.x * QROWS;
    const float* L = g_logits + bh * (S * S);
    float* A = g_attn + bh * (S * S);

    __shared__ float rows[QROWS + 2][S + 2];
    const int tid = threadIdx.x;
    const int c = tid * 4;
    const int climit = (q0 + 16 < S) ? (q0 + 16) : S;  // cols we actually need

#pragma unroll
    for (int r = 0; r < QROWS + 2; r++) {
        int qp = q0 - 2 + r;
        if (tid == 0) rows[r][0] = 0.f;
        if (tid == 1) rows[r][S + 1] = 0.f;
        if (c >= climit) continue;
        float4 val = make_float4(0.f, 0.f, 0.f, 0.f);
        if (qp >= 0) {
            val = *(const float4*)&L[qp * S + c];
            // zero above-diagonal (also guards unwritten upper tiles)
            if (c + 0 > qp) val.x = 0.f;
            if (c + 1 > qp) val.y = 0.f;
            if (c + 2 > qp) val.z = 0.f;
            if (c + 3 > qp) val.w = 0.f;
        }
        rows[r][c + 1] = val.x; rows[r][c + 2] = val.y;
        rows[r][c + 3] = val.z; rows[r][c + 4] = val.w;
    }

    float wv[9];
#pragma unroll
    for (int t = 0; t < 9; t++) wv[t] = kq_w[h * 9 + t];
    const float bias = kq_b[h];
    __syncthreads();

    for (int i = 0; i < QROWS; i++) {
        const int q = q0 + i;
        const int kmax = (q + 1 < S - 1) ? (q + 1) : (S - 1);
        float cv[4];
        float mxl = -1e30f;
#pragma unroll
        for (int u = 0; u < 4; u++) {
            int k = c + u;
            if (k <= kmax) {
                const float* r0 = &rows[i][k];
                const float* r1 = &rows[i + 1][k];
                const float* r2 = &rows[i + 2][k];
                cv[u] = wv[0] * r0[0] + wv[1] * r0[1] + wv[2] * r0[2]
                      + wv[3] * r1[0] + wv[4] * r1[1] + wv[5] * r1[2]
                      + wv[6] * r2[0] + wv[7] * r2[1] + wv[8] * r2[2] + bias;
                mxl = fmaxf(mxl, cv[u]);
            } else cv[u] = 0.f;
        }
        float mx = fmaxf(block_reduce_max(mxl), bias);
        float e[4]; float esum = 0.f;
#pragma unroll
        for (int u = 0; u < 4; u++) {
            if (c + u <= kmax) { e[u] = __expf(cv[u] - mx); esum += e[u]; }
            else e[u] = 0.f;
        }
        int cnt = S - 2 - q; if (cnt < 0) cnt = 0;
        float eb = __expf(bias - mx);
        float sum = block_reduce_sum(esum) + (float)cnt * eb;
        float inv = 1.f / sum;
        float constv = eb * inv;

        int Klim = ((q >> 6) << 6) + 128; if (Klim > S) Klim = S;
        if (c < Klim) {
            float4 o;
            o.x = (c + 0 <= kmax) ? e[0] * inv : constv;
            o.y = (c + 1 <= kmax) ? e[1] * inv : constv;
            o.z = (c + 2 <= kmax) ? e[2] * inv : constv;
            o.w = (c + 3 <= kmax) ? e[3] * inv : constv;
            *(float4*)&A[q * S + c] = o;
        }
        if (tid == 0) g_rowconst[bh * S + q] = constv;
    }
}

// ============================================================================
// Kernel 4: V suffix sums at 64-row chunk boundaries (17 per head).
// ============================================================================
__global__ __launch_bounds__(256) void suffv_kernel()
{
    const int bh = blockIdx.x;
    const int tid = threadIdx.x;
    __shared__ float cs[16][64];
    const int d = tid & 63;
    const int cg = tid >> 6;  // 0..3
    const float* V = g_v + bh * (S * HD);
    for (int ci = cg; ci < 16; ci += 4) {
        float s = 0.f;
#pragma unroll 8
        for (int r = 0; r < 64; r++) s += V[(ci * 64 + r) * HD + d];
        cs[ci][d] = s;
    }
    __syncthreads();
    if (tid < 64) {
        float suf = 0.f;
        g_suffV[(bh * 17 + 16) * HD + tid] = 0.f;
        for (int ci = 15; ci >= 0; ci--) {
            suf += cs[ci][tid];
            g_suffV[(bh * 17 + ci) * HD + tid] = suf;
        }
    }
}

// ============================================================================
// Kernel 5: paired-head mix + attn@V (k < Klim) + constant-tail + DyT.
// Block: 64 q-rows x 128 cols (two heads' 64 dims). 256 threads, 8x4/thread.
// ============================================================================
__global__ __launch_bounds__(256) void pv_pair_kernel(
    const float* __restrict__ mix_w, const float* __restrict__ mix_b,
    const float* __restrict__ dyt_alpha, const float* __restrict__ dyt_w,
    const float* __restrict__ dyt_b, const float* __restrict__ depth_scale)
{
    const int pair = blockIdx.z;           // 0..15
    const int b = pair >> 3, hp = pair & 7;
    const int h0 = hp * 2, h1 = h0 + 1;
    const int bh0 = b * 16 + h0, bh1 = bh0 + 1;
    const int Q0 = (gridDim.y - 1 - blockIdx.y) * 64;   // big tiles first
    int Klim = Q0 + 128; if (Klim > S) Klim = S;
    const int cidx = Klim >> 6;

    const float* A0 = g_attn + bh0 * (S * S);
    const float* A1 = g_attn + bh1 * (S * S);
    const float* V0 = g_v + bh0 * (S * HD);
    const float* V1 = g_v + bh1 * (S * HD);

    const float m00 = mix_w[h0 * 2 + 0], m01 = mix_w[h0 * 2 + 1];
    const float m10 = mix_w[h1 * 2 + 0], m11 = mix_w[h1 * 2 + 1];
    const float mb0 = mix_b[h0], mb1 = mix_b[h1];
    const float alpha = dyt_alpha[0], ds = depth_scale[0];

    __shared__ float Am[16][132];   // [kk][head*66 + row]
    __shared__ float Bv[16][128];   // [kk][head*64 + d]

    const int tid = threadIdx.x;
    const int ar = tid >> 2, ac = (tid & 3) * 4;       // A load: row, k-offset
    const int vr = tid >> 4, vc = (tid & 15) * 4;      // V load
    const int tx = tid & 31, ty = tid >> 5;            // compute map
    const int dcol = tx * 4;                            // 0..124
    const int half = (dcol >= 64) ? 1 : 0;

    float acc[8][4];
#pragma unroll
    for (int i = 0; i < 8; i++)
#pragma unroll
        for (int j = 0; j < 4; j++) acc[i][j] = 0.f;

    for (int k0 = 0; k0 < Klim; k0 += 16) {
        float4 a0 = *(const float4*)&A0[(Q0 + ar) * S + k0 + ac];
        float4 a1 = *(const float4*)&A1[(Q0 + ar) * S + k0 + ac];
        Am[ac + 0][ar] = m00 * a0.x + m01 * a1.x;
        Am[ac + 1][ar] = m00 * a0.y + m01 * a1.y;
        Am[ac + 2][ar] = m00 * a0.z + m01 * a1.z;
        Am[ac + 3][ar] = m00 * a0.w + m01 * a1.w;
        Am[ac + 0][66 + ar] = m10 * a0.x + m11 * a1.x;
        Am[ac + 1][66 + ar] = m10 * a0.y + m11 * a1.y;
        Am[ac + 2][66 + ar] = m10 * a0.z + m11 * a1.z;
        Am[ac + 3][66 + ar] = m10 * a0.w + m11 * a1.w;
        *(float4*)&Bv[vr][vc]      = *(const float4*)&V0[(k0 + vr) * HD + vc];
        *(float4*)&Bv[vr][64 + vc] = *(const float4*)&V1[(k0 + vr) * HD + vc];
        __syncthreads();
#pragma unroll
        for (int kk = 0; kk < 16; kk++) {
            float4 bv = *(const float4*)&Bv[kk][dcol];
            float brr[4] = {bv.x, bv.y, bv.z, bv.w};
            const float* ap = &Am[kk][half * 66 + ty * 8];
#pragma unroll
            for (int i = 0; i < 8; i++) {
                float av = ap[i];
#pragma unroll
                for (int j = 0; j < 4; j++) acc[i][j] += av * brr[j];
            }
        }
        __syncthreads();
    }

    // epilogue
    const float* suff = g_suffV + ((half ? bh1 : bh0) * 17 + cidx) * HD;
    const float* csum = g_suffV + ((half ? bh1 : bh0) * 17 + 0) * HD;
    const float* rc0 = g_rowconst + bh0 * S;
    const float* rc1 = g_rowconst + bh1 * S;
    const float mb = half ? mb1 : mb0;
    const float ma = half ? m10 : m00;
    const float mbx = half ? m11 : m01;
    float* O = g_attout + b * (S * E) + h0 * HD;   // col e = h0*64 + dcol

#pragma unroll
    for (int i = 0; i < 8; i++) {
        int q = Q0 + ty * 8 + i;
        float cmix = ma * rc0[q] + mbx * rc1[q];
#pragma unroll
        for (int j = 0; j < 4; j++) {
            int dc = dcol + j;
            int d = dc & 63;
            float v = acc[i][j] + cmix * suff[d] + mb * csum[d];
            v = tanhf(alpha * v) * dyt_w[d] + dyt_b[d];
            v *= ds;
            O[q * E + dc] = v;
        }
    }
}

// ============================================================================
// Kernel 6: output projection  d_out = attout @ Wo + bo
// ============================================================================
__global__ __launch_bounds__(256) void out_proj_kernel(
    const float* __restrict__ Wo, const float* __restrict__ bo,
    float* __restrict__ out)
{
    __shared__ float As[8][128];
    __shared__ float Bs[8][128];

    const int tid  = threadIdx.x;
    const int row0 = blockIdx.y * 128;
    const int col0 = blockIdx.x * 128;
    const int tx = tid & 15, ty = tid >> 4;
    const int aRow = tid >> 1,  aCol = (tid & 1) * 4;
    const int bRow = tid >> 5,  bCol = (tid & 31) * 4;

    float acc[8][8];
#pragma unroll
    for (int i = 0; i < 8; i++)
#pragma unroll
        for (int j = 0; j < 8; j++) acc[i][j] = 0.f;

    const float* Aptr = g_attout + (row0 + aRow) * E + aCol;
    const float* Bptr = Wo + bRow * E + col0 + bCol;

    for (int k0 = 0; k0 < E; k0 += 8) {
        float4 a = *(const float4*)(Aptr + k0);
        As[aCol + 0][aRow] = a.x; As[aCol + 1][aRow] = a.y;
        As[aCol + 2][aRow] = a.z; As[aCol + 3][aRow] = a.w;
        *(float4*)&Bs[bRow][bCol] = *(const float4*)(Bptr + k0 * E);
        __syncthreads();
#pragma unroll
        for (int kk = 0; kk < 8; kk++) {
            float4 a0 = *(const float4*)&As[kk][ty * 8];
            float4 a1 = *(const float4*)&As[kk][ty * 8 + 4];
            float4 b0 = *(const float4*)&Bs[kk][tx * 8];
            float4 b1 = *(const float4*)&Bs[kk][tx * 8 + 4];
            float ar[8] = {a0.x, a0.y, a0.z, a0.w, a1.x, a1.y, a1.z, a1.w};
            float br[8] = {b0.x, b0.y, b0.z, b0.w, b1.x, b1.y, b1.z, b1.w};
#pragma unroll
            for (int i = 0; i < 8; i++)
#pragma unroll
                for (int j = 0; j < 8; j++) acc[i][j] += ar[i] * br[j];
        }
        __syncthreads();
    }

#pragma unroll
    for (int i = 0; i < 8; i++) {
        int m = row0 + ty * 8 + i;
#pragma unroll
        for (int j = 0; j < 8; j++) {
            int n = col0 + tx * 8 + j;
            out[m * E + n] = acc[i][j] + bo[n];
        }
    }
}

// ============================================================================
// Launch
// ============================================================================
extern "C" void kernel_launch(void* const* d_in, const int* in_sizes, int n_in,
                              void* d_out, int out_size)
{
    const float* Q   = (const float*)d_in[0];
    const float* K   = (const float*)d_in[1];
    const float* V   = (const float*)d_in[2];
    const float* Wq  = (const float*)d_in[3];
    const float* bq  = (const float*)d_in[4];
    const float* Wk  = (const float*)d_in[5];
    const float* bk  = (const float*)d_in[6];
    const float* Wv  = (const float*)d_in[7];
    const float* bv  = (const float*)d_in[8];
    const float* Wo  = (const float*)d_in[9];
    const float* bo  = (const float*)d_in[10];
    const float* kq_w = (const float*)d_in[11];
    const float* kq_b = (const float*)d_in[12];
    const float* mix_w = (const float*)d_in[13];
    const float* mix_b = (const float*)d_in[14];
    const float* dyt_alpha = (const float*)d_in[15];
    const float* dyt_w = (const float*)d_in[16];
    const float* dyt_b = (const float*)d_in[17];
    const float* depth_scale = (const float*)d_in[18];

    proj_qkv_kernel<<<dim3(8, 16, 3), 256>>>(Q, K, V, Wq, Wk, Wv, bq, bk, bv);
    suffv_kernel<<<BH, 256>>>();
    logits_kernel<<<dim3(36, BH), 256>>>();
    conv_softmax_kernel<<<dim3(S / QROWS, BH), 256>>>(kq_w, kq_b);
    pv_pair_kernel<<<dim3(1, S / 64, BH / 2), 256>>>(mix_w, mix_b, dyt_alpha, dyt_w, dyt_b, depth_scale);
    out_proj_kernel<<<dim3(8, 16), 256>>>(Wo, bo, (float*)d_out);
}

// round 4
// speedup vs baseline: 1.8367x; 1.6627x over previous
#include <cuda_runtime.h>
#include <cuda_bf16.h>
#include <math.h>
#include <cstdint>

#define S 1024
#define E 1024
#define H 16
#define HD 64
#define BATCH 2
#define BH (BATCH * H)     // 32
#define M_TOT (BATCH * S)  // 2048

// ---------------- scratch (device globals; no runtime allocation) ----------
__device__ __align__(16) float g_q[BH * S * HD];
__device__ __align__(16) float g_k[BH * S * HD];
__device__ __align__(16) float g_v[BH * S * HD];
__device__ __align__(16) float g_logits[BH * S * S];
__device__ __align__(16) float g_attn[BH * S * S];
__device__ __align__(16) float g_rowconst[BH * S];
__device__ __align__(16) float g_suffV[BH * 17 * HD];
__device__ __align__(16) __nv_bfloat16 g_ah[3 * M_TOT * E];
__device__ __align__(16) __nv_bfloat16 g_al[3 * M_TOT * E];
__device__ __align__(16) __nv_bfloat16 g_wth[4 * E * E];   // W^T [n][k]
__device__ __align__(16) __nv_bfloat16 g_wtl[4 * E * E];
__device__ __align__(16) __nv_bfloat16 g_aoh[M_TOT * E];
__device__ __align__(16) __nv_bfloat16 g_aol[M_TOT * E];

// ============================ PTX helpers ===================================
__device__ __forceinline__ uint32_t smem_u32(const void* p) {
    uint32_t a;
    asm("{ .reg .u64 t; cvta.to.shared.u64 t, %1; cvt.u32.u64 %0, t; }" : "=r"(a) : "l"(p));
    return a;
}
__device__ __forceinline__ void ldsm_x4(uint32_t* r, uint32_t addr) {
    asm volatile("ldmatrix.sync.aligned.m8n8.x4.shared.b16 {%0,%1,%2,%3}, [%4];"
        : "=r"(r[0]), "=r"(r[1]), "=r"(r[2]), "=r"(r[3]) : "r"(addr));
}
__device__ __forceinline__ void mma_bf16(float* c, const uint32_t* a, const uint32_t* b) {
    asm volatile("mma.sync.aligned.m16n8k16.row.col.f32.bf16.bf16.f32 "
        "{%0,%1,%2,%3}, {%4,%5,%6,%7}, {%8,%9}, {%0,%1,%2,%3};"
        : "+f"(c[0]), "+f"(c[1]), "+f"(c[2]), "+f"(c[3])
        : "r"(a[0]), "r"(a[1]), "r"(a[2]), "r"(a[3]), "r"(b[0]), "r"(b[1]));
}
__device__ __forceinline__ void cp16(uint32_t saddr, const void* g) {
    asm volatile("cp.async.cg.shared.global [%0], [%1], 16;" :: "r"(saddr), "l"(g));
}

// GEMM geometry: 128x128 block, BK=32, 8 warps (4m x 2n), warp 32x64.
#define PITCH 40                 // bf16 per smem row (80 B: conflict-free ldmatrix)
#define TILE_B 10240             // 128 * PITCH * 2
#define STAGE_B 40960            // 4 tiles (Ah, Al, Bh, Bl)
#define GEMM_SMEM (2 * STAGE_B)  // 81920

// ============================================================================
// prep: split f32 -> bf16 hi/lo (Q, K, V inputs)
// ============================================================================
__global__ __launch_bounds__(256) void asplit_kernel(
    const float* __restrict__ Q, const float* __restrict__ K, const float* __restrict__ V)
{
    int z = blockIdx.z;
    const float* X = (z == 0) ? Q : (z == 1) ? K : V;
    __nv_bfloat16* hp = g_ah + (size_t)z * M_TOT * E;
    __nv_bfloat16* lp = g_al + (size_t)z * M_TOT * E;
    int i = (blockIdx.x * 256 + threadIdx.x) * 4;
    float4 v = *(const float4*)(X + i);
    float vv[4] = {v.x, v.y, v.z, v.w};
#pragma unroll
    for (int j = 0; j < 4; j++) {
        __nv_bfloat16 h = __float2bfloat16(vv[j]);
        hp[i + j] = h;
        lp[i + j] = __float2bfloat16(vv[j] - __bfloat162float(h));
    }
}

// ============================================================================
// prep: transpose + split weights: Wt[n][k] = W[k][n], bf16 hi/lo
// ============================================================================
__global__ void wsplit_kernel(const float* __restrict__ Wq, const float* __restrict__ Wk,
                              const float* __restrict__ Wv, const float* __restrict__ Wo)
{
    int z = blockIdx.z;
    const float* W = (z == 0) ? Wq : (z == 1) ? Wk : (z == 2) ? Wv : Wo;
    __nv_bfloat16* th = g_wth + (size_t)z * E * E;
    __nv_bfloat16* tl = g_wtl + (size_t)z * E * E;
    __shared__ float tile[32][33];
    int n0 = blockIdx.x * 32, k0 = blockIdx.y * 32;
    int tx = threadIdx.x, ty = threadIdx.y;
    for (int i = ty; i < 32; i += 8)
        tile[i][tx] = W[(size_t)(k0 + i) * E + n0 + tx];
    __syncthreads();
    for (int i = ty; i < 32; i += 8) {
        float v = tile[tx][i];  // W[k0+tx][n0+i]
        __nv_bfloat16 h = __float2bfloat16(v);
        th[(size_t)(n0 + i) * E + k0 + tx] = h;
        tl[(size_t)(n0 + i) * E + k0 + tx] = __float2bfloat16(v - __bfloat162float(h));
    }
}

// ============================================================================
// mma.sync GEMM core: C[128x128] += (Ah+Al)[128xE] @ (Bh+Bl)[128xE]^T
// ============================================================================
__device__ __forceinline__ void gemm_load_stage(uint32_t sbs,
    const __nv_bfloat16* __restrict__ Ah, const __nv_bfloat16* __restrict__ Al,
    const __nv_bfloat16* __restrict__ Bh, const __nv_bfloat16* __restrict__ Bl,
    int m0, int n0, int k0)
{
    int t = threadIdx.x;
#pragma unroll
    for (int i = 0; i < 2; i++) {
        int idx = t + i * 256;
        int r = idx >> 2, c = (idx & 3) * 8;
        uint32_t so = (uint32_t)(r * PITCH + c) * 2;
        cp16(sbs + so,              Ah + (size_t)(m0 + r) * E + k0 + c);
        cp16(sbs + TILE_B + so,     Al + (size_t)(m0 + r) * E + k0 + c);
        cp16(sbs + 2 * TILE_B + so, Bh + (size_t)(n0 + r) * E + k0 + c);
        cp16(sbs + 3 * TILE_B + so, Bl + (size_t)(n0 + r) * E + k0 + c);
    }
}

__device__ __forceinline__ void gemm_compute_stage(
    uint32_t sb, int wm, int wn, int a_r, int a_c8, int b_r, int b_c8,
    float cacc[2][8][4])
{
#pragma unroll
    for (int kk = 0; kk < 32; kk += 16) {
        uint32_t ah[2][4], al[2][4], bh[4][4], bl[4][4];
#pragma unroll
        for (int mt = 0; mt < 2; mt++) {
            uint32_t ro = (uint32_t)((wm * 32 + mt * 16 + a_r) * PITCH + kk + a_c8) * 2;
            ldsm_x4(ah[mt], sb + ro);
            ldsm_x4(al[mt], sb + TILE_B + ro);
        }
#pragma unroll
        for (int i = 0; i < 4; i++) {
            uint32_t ro = (uint32_t)((wn * 64 + i * 16 + b_r) * PITCH + kk + b_c8) * 2;
            ldsm_x4(bh[i], sb + 2 * TILE_B + ro);
            ldsm_x4(bl[i], sb + 3 * TILE_B + ro);
        }
#pragma unroll
        for (int mt = 0; mt < 2; mt++)
#pragma unroll
            for (int nt = 0; nt < 8; nt++) {
                const uint32_t* bp  = &bh[nt >> 1][(nt & 1) * 2];
                const uint32_t* blp = &bl[nt >> 1][(nt & 1) * 2];
                mma_bf16(cacc[mt][nt], ah[mt], bp);
                mma_bf16(cacc[mt][nt], al[mt], bp);
                mma_bf16(cacc[mt][nt], ah[mt], blp);
            }
    }
}

__device__ __forceinline__ void gemm_mainloop(uint32_t sb,
    const __nv_bfloat16* Ah, const __nv_bfloat16* Al,
    const __nv_bfloat16* Bh, const __nv_bfloat16* Bl,
    int m0, int n0, int wm, int wn, int a_r, int a_c8, int b_r, int b_c8,
    float cacc[2][8][4])
{
    gemm_load_stage(sb, Ah, Al, Bh, Bl, m0, n0, 0);
    asm volatile("cp.async.commit_group;" ::: "memory");
    for (int c = 0; c < 32; c++) {
        if (c + 1 < 32) {
            gemm_load_stage(sb + ((c + 1) & 1) * STAGE_B, Ah, Al, Bh, Bl, m0, n0, (c + 1) * 32);
            asm volatile("cp.async.commit_group;" ::: "memory");
            asm volatile("cp.async.wait_group 1;" ::: "memory");
        } else {
            asm volatile("cp.async.wait_group 0;" ::: "memory");
        }
        __syncthreads();
        gemm_compute_stage(sb + (c & 1) * STAGE_B, wm, wn, a_r, a_c8, b_r, b_c8, cacc);
        __syncthreads();
    }
}

// ============================================================================
// GEMM kernel A: QKV projections -> scatter f32 to g_q/g_k/g_v [bh][s][d]
// ============================================================================
__global__ void __launch_bounds__(256, 2) gemm_qkv_tc(
    const float* __restrict__ bq, const float* __restrict__ bk, const float* __restrict__ bv)
{
    extern __shared__ __align__(16) char smem[];
    uint32_t sb = smem_u32(smem);
    int z = blockIdx.z;
    int m0 = blockIdx.y * 128, n0 = blockIdx.x * 128;
    const __nv_bfloat16* Ah = g_ah + (size_t)z * M_TOT * E;
    const __nv_bfloat16* Al = g_al + (size_t)z * M_TOT * E;
    const __nv_bfloat16* Bh = g_wth + (size_t)z * E * E;
    const __nv_bfloat16* Bl = g_wtl + (size_t)z * E * E;
    const float* bias = (z == 0) ? bq : (z == 1) ? bk : bv;
    float* out = (z == 0) ? g_q : (z == 1) ? g_k : g_v;

    int lane = threadIdx.x & 31, wid = threadIdx.x >> 5;
    int wm = wid & 3, wn = wid >> 2;
    int a_r = lane & 15, a_c8 = (lane >> 4) * 8;
    int b_r = (lane & 7) | ((lane >> 4) << 3), b_c8 = ((lane >> 3) & 1) * 8;

    float cacc[2][8][4] = {};
    gemm_mainloop(sb, Ah, Al, Bh, Bl, m0, n0, wm, wn, a_r, a_c8, b_r, b_c8, cacc);

#pragma unroll
    for (int mt = 0; mt < 2; mt++)
#pragma unroll
        for (int nt = 0; nt < 8; nt++) {
            int m = m0 + wm * 32 + mt * 16 + (lane >> 2);
            int n = n0 + wn * 64 + nt * 8 + (lane & 3) * 2;
            int bb = m >> 10, s = m & 1023, h = n >> 6, d = n & 63;
            float* op = out + (((size_t)bb * H + h) * S + s) * HD + d;
            float b0 = bias[n], b1 = bias[n + 1];
            float2 v0 = make_float2(cacc[mt][nt][0] + b0, cacc[mt][nt][1] + b1);
            float2 v1 = make_float2(cacc[mt][nt][2] + b0, cacc[mt][nt][3] + b1);
            *(float2*)op = v0;
            *(float2*)(op + 8 * HD) = v1;
        }
}

// ============================================================================
// GEMM kernel B: output projection -> d_out = AO @ Wo + bo
// ============================================================================
__global__ void __launch_bounds__(256, 2) gemm_out_tc(
    const float* __restrict__ bo, float* __restrict__ dout)
{
    extern __shared__ __align__(16) char smem[];
    uint32_t sb = smem_u32(smem);
    int m0 = blockIdx.y * 128, n0 = blockIdx.x * 128;
    const __nv_bfloat16* Bh = g_wth + (size_t)3 * E * E;
    const __nv_bfloat16* Bl = g_wtl + (size_t)3 * E * E;

    int lane = threadIdx.x & 31, wid = threadIdx.x >> 5;
    int wm = wid & 3, wn = wid >> 2;
    int a_r = lane & 15, a_c8 = (lane >> 4) * 8;
    int b_r = (lane & 7) | ((lane >> 4) << 3), b_c8 = ((lane >> 3) & 1) * 8;

    float cacc[2][8][4] = {};
    gemm_mainloop(sb, g_aoh, g_aol, Bh, Bl, m0, n0, wm, wn, a_r, a_c8, b_r, b_c8, cacc);

#pragma unroll
    for (int mt = 0; mt < 2; mt++)
#pragma unroll
        for (int nt = 0; nt < 8; nt++) {
            int m = m0 + wm * 32 + mt * 16 + (lane >> 2);
            int n = n0 + wn * 64 + nt * 8 + (lane & 3) * 2;
            float* op = dout + (size_t)m * E + n;
            float b0 = bo[n], b1 = bo[n + 1];
            float2 v0 = make_float2(cacc[mt][nt][0] + b0, cacc[mt][nt][1] + b1);
            float2 v1 = make_float2(cacc[mt][nt][2] + b0, cacc[mt][nt][3] + b1);
            *(float2*)op = v0;
            *(float2*)(op + 8 * E) = v1;
        }
}

// ============================================================================
// logits (lower-triangular tiles only), scalar fp32
// ============================================================================
__global__ __launch_bounds__(256) void logits_kernel()
{
    const int bh = blockIdx.y;
    int t = blockIdx.x, r = 0;
    while (t > r) { t -= r + 1; r++; }
    const int row0 = r * 128;
    const int col0 = t * 128;

    float* L = g_logits + (size_t)bh * (S * S);
    const float* qp = g_q + bh * (S * HD);
    const float* kp = g_k + bh * (S * HD);

    __shared__ float As[8][128];
    __shared__ float Bs[8][128];
    const int tid = threadIdx.x;
    const int tx = tid & 15, ty = tid >> 4;
    const int lRow = tid >> 1, lCol = (tid & 1) * 4;

    float acc[8][8];
#pragma unroll
    for (int i = 0; i < 8; i++)
#pragma unroll
        for (int j = 0; j < 8; j++) acc[i][j] = 0.f;

    for (int d0 = 0; d0 < HD; d0 += 8) {
        float4 a = *(const float4*)&qp[(row0 + lRow) * HD + d0 + lCol];
        As[lCol + 0][lRow] = a.x; As[lCol + 1][lRow] = a.y;
        As[lCol + 2][lRow] = a.z; As[lCol + 3][lRow] = a.w;
        float4 b = *(const float4*)&kp[(col0 + lRow) * HD + d0 + lCol];
        Bs[lCol + 0][lRow] = b.x; Bs[lCol + 1][lRow] = b.y;
        Bs[lCol + 2][lRow] = b.z; Bs[lCol + 3][lRow] = b.w;
        __syncthreads();
#pragma unroll
        for (int kk = 0; kk < 8; kk++) {
            float4 a0 = *(const float4*)&As[kk][ty * 8];
            float4 a1 = *(const float4*)&As[kk][ty * 8 + 4];
            float4 b0 = *(const float4*)&Bs[kk][tx * 8];
            float4 b1 = *(const float4*)&Bs[kk][tx * 8 + 4];
            float ar[8] = {a0.x, a0.y, a0.z, a0.w, a1.x, a1.y, a1.z, a1.w};
            float br[8] = {b0.x, b0.y, b0.z, b0.w, b1.x, b1.y, b1.z, b1.w};
#pragma unroll
            for (int i = 0; i < 8; i++)
#pragma unroll
                for (int j = 0; j < 8; j++) acc[i][j] += ar[i] * br[j];
        }
        __syncthreads();
    }

    const float scale = 0.125f;
#pragma unroll
    for (int i = 0; i < 8; i++) {
        int m = row0 + ty * 8 + i;
#pragma unroll
        for (int j = 0; j < 8; j++) {
            int n = col0 + tx * 8 + j;
            L[(size_t)m * S + n] = (n <= m) ? acc[i][j] * scale : 0.f;
        }
    }
}

// ============================================================================
// conv + analytic-constant softmax
// ============================================================================
__device__ __forceinline__ float block_reduce_max(float v) {
    __shared__ float sm[8];
    int lane = threadIdx.x & 31, wid = threadIdx.x >> 5;
#pragma unroll
    for (int o = 16; o; o >>= 1) v = fmaxf(v, __shfl_xor_sync(0xffffffffu, v, o));
    if (lane == 0) sm[wid] = v;
    __syncthreads();
    if (wid == 0) {
        v = sm[lane & 7];
#pragma unroll
        for (int o = 4; o; o >>= 1) v = fmaxf(v, __shfl_xor_sync(0xffffffffu, v, o));
        if (lane == 0) sm[0] = v;
    }
    __syncthreads();
    v = sm[0];
    __syncthreads();
    return v;
}
__device__ __forceinline__ float block_reduce_sum(float v) {
    __shared__ float ss[8];
    int lane = threadIdx.x & 31, wid = threadIdx.x >> 5;
#pragma unroll
    for (int o = 16; o; o >>= 1) v += __shfl_xor_sync(0xffffffffu, v, o);
    if (lane == 0) ss[wid] = v;
    __syncthreads();
    if (wid == 0) {
        v = ss[lane & 7];
#pragma unroll
        for (int o = 4; o; o >>= 1) v += __shfl_xor_sync(0xffffffffu, v, o);
        if (lane == 0) ss[0] = v;
    }
    __syncthreads();
    v = ss[0];
    __syncthreads();
    return v;
}

#define QROWS 8
__global__ __launch_bounds__(256) void conv_softmax_kernel(
    const float* __restrict__ kq_w, const float* __restrict__ kq_b)
{
    const int bh = blockIdx.y;
    const int h  = bh & 15;
    const int q0 = blockIdx.x * QROWS;
    const float* L = g_logits + (size_t)bh * (S * S);
    float* A = g_attn + (size_t)bh * (S * S);

    __shared__ float rows[QROWS + 2][S + 2];
    const int tid = threadIdx.x;
    const int c = tid * 4;
    const int climit = (q0 + 16 < S) ? (q0 + 16) : S;

#pragma unroll
    for (int r = 0; r < QROWS + 2; r++) {
        int qp = q0 - 2 + r;
        if (tid == 0) rows[r][0] = 0.f;
        if (tid == 1) rows[r][S + 1] = 0.f;
        if (c >= climit) continue;
        float4 val = make_float4(0.f, 0.f, 0.f, 0.f);
        if (qp >= 0) {
            val = *(const float4*)&L[(size_t)qp * S + c];
            if (c + 0 > qp) val.x = 0.f;
            if (c + 1 > qp) val.y = 0.f;
            if (c + 2 > qp) val.z = 0.f;
            if (c + 3 > qp) val.w = 0.f;
        }
        rows[r][c + 1] = val.x; rows[r][c + 2] = val.y;
        rows[r][c + 3] = val.z; rows[r][c + 4] = val.w;
    }

    float wv[9];
#pragma unroll
    for (int t = 0; t < 9; t++) wv[t] = kq_w[h * 9 + t];
    const float bias = kq_b[h];
    __syncthreads();

    for (int i = 0; i < QROWS; i++) {
        const int q = q0 + i;
        const int kmax = (q + 1 < S - 1) ? (q + 1) : (S - 1);
        float cv[4];
        float mxl = -1e30f;
#pragma unroll
        for (int u = 0; u < 4; u++) {
            int k = c + u;
            if (k <= kmax) {
                const float* r0 = &rows[i][k];
                const float* r1 = &rows[i + 1][k];
                const float* r2 = &rows[i + 2][k];
                cv[u] = wv[0] * r0[0] + wv[1] * r0[1] + wv[2] * r0[2]
                      + wv[3] * r1[0] + wv[4] * r1[1] + wv[5] * r1[2]
                      + wv[6] * r2[0] + wv[7] * r2[1] + wv[8] * r2[2] + bias;
                mxl = fmaxf(mxl, cv[u]);
            } else cv[u] = 0.f;
        }
        float mx = fmaxf(block_reduce_max(mxl), bias);
        float e[4]; float esum = 0.f;
#pragma unroll
        for (int u = 0; u < 4; u++) {
            if (c + u <= kmax) { e[u] = __expf(cv[u] - mx); esum += e[u]; }
            else e[u] = 0.f;
        }
        int cnt = S - 2 - q; if (cnt < 0) cnt = 0;
        float eb = __expf(bias - mx);
        float sum = block_reduce_sum(esum) + (float)cnt * eb;
        float inv = 1.f / sum;
        float constv = eb * inv;

        int Klim = ((q >> 6) << 6) + 128; if (Klim > S) Klim = S;
        if (c < Klim) {
            float4 o;
            o.x = (c + 0 <= kmax) ? e[0] * inv : constv;
            o.y = (c + 1 <= kmax) ? e[1] * inv : constv;
            o.z = (c + 2 <= kmax) ? e[2] * inv : constv;
            o.w = (c + 3 <= kmax) ? e[3] * inv : constv;
            *(float4*)&A[(size_t)q * S + c] = o;
        }
        if (tid == 0) g_rowconst[bh * S + q] = constv;
    }
}

// ============================================================================
// V suffix sums at 64-row chunk boundaries
// ============================================================================
__global__ __launch_bounds__(256) void suffv_kernel()
{
    const int bh = blockIdx.x;
    const int tid = threadIdx.x;
    __shared__ float cs[16][64];
    const int d = tid & 63;
    const int cg = tid >> 6;
    const float* V = g_v + bh * (S * HD);
    for (int ci = cg; ci < 16; ci += 4) {
        float s = 0.f;
#pragma unroll 8
        for (int r = 0; r < 64; r++) s += V[(ci * 64 + r) * HD + d];
        cs[ci][d] = s;
    }
    __syncthreads();
    if (tid < 64) {
        float suf = 0.f;
        g_suffV[(bh * 17 + 16) * HD + tid] = 0.f;
        for (int ci = 15; ci >= 0; ci--) {
            suf += cs[ci][tid];
            g_suffV[(bh * 17 + ci) * HD + tid] = suf;
        }
    }
}

// ============================================================================
// paired-head mix + attn@V (k < Klim) + constant-tail + DyT -> bf16 hi/lo
// ============================================================================
__global__ __launch_bounds__(256) void pv_pair_kernel(
    const float* __restrict__ mix_w, const float* __restrict__ mix_b,
    const float* __restrict__ dyt_alpha, const float* __restrict__ dyt_w,
    const float* __restrict__ dyt_b, const float* __restrict__ depth_scale)
{
    const int pair = blockIdx.z;
    const int b = pair >> 3, hp = pair & 7;
    const int h0 = hp * 2, h1 = h0 + 1;
    const int bh0 = b * 16 + h0, bh1 = bh0 + 1;
    const int Q0 = (gridDim.y - 1 - blockIdx.y) * 64;
    int Klim = Q0 + 128; if (Klim > S) Klim = S;
    const int cidx = Klim >> 6;

    const float* A0 = g_attn + (size_t)bh0 * (S * S);
    const float* A1 = g_attn + (size_t)bh1 * (S * S);
    const float* V0 = g_v + bh0 * (S * HD);
    const float* V1 = g_v + bh1 * (S * HD);

    const float m00 = mix_w[h0 * 2 + 0], m01 = mix_w[h0 * 2 + 1];
    const float m10 = mix_w[h1 * 2 + 0], m11 = mix_w[h1 * 2 + 1];
    const float mb0 = mix_b[h0], mb1 = mix_b[h1];
    const float alpha = dyt_alpha[0], ds = depth_scale[0];

    __shared__ float Am[16][132];
    __shared__ float Bv[16][128];

    const int tid = threadIdx.x;
    const int ar = tid >> 2, ac = (tid & 3) * 4;
    const int vr = tid >> 4, vc = (tid & 15) * 4;
    const int tx = tid & 31, ty = tid >> 5;
    const int dcol = tx * 4;
    const int half = (dcol >= 64) ? 1 : 0;

    float acc[8][4];
#pragma unroll
    for (int i = 0; i < 8; i++)
#pragma unroll
        for (int j = 0; j < 4; j++) acc[i][j] = 0.f;

    for (int k0 = 0; k0 < Klim; k0 += 16) {
        float4 a0 = *(const float4*)&A0[(size_t)(Q0 + ar) * S + k0 + ac];
        float4 a1 = *(const float4*)&A1[(size_t)(Q0 + ar) * S + k0 + ac];
        Am[ac + 0][ar] = m00 * a0.x + m01 * a1.x;
        Am[ac + 1][ar] = m00 * a0.y + m01 * a1.y;
        Am[ac + 2][ar] = m00 * a0.z + m01 * a1.z;
        Am[ac + 3][ar] = m00 * a0.w + m01 * a1.w;
        Am[ac + 0][66 + ar] = m10 * a0.x + m11 * a1.x;
        Am[ac + 1][66 + ar] = m10 * a0.y + m11 * a1.y;
        Am[ac + 2][66 + ar] = m10 * a0.z + m11 * a1.z;
        Am[ac + 3][66 + ar] = m10 * a0.w + m11 * a1.w;
        *(float4*)&Bv[vr][vc]      = *(const float4*)&V0[(k0 + vr) * HD + vc];
        *(float4*)&Bv[vr][64 + vc] = *(const float4*)&V1[(k0 + vr) * HD + vc];
        __syncthreads();
#pragma unroll
        for (int kk = 0; kk < 16; kk++) {
            float4 bv = *(const float4*)&Bv[kk][dcol];
            float brr[4] = {bv.x, bv.y, bv.z, bv.w};
            const float* ap = &Am[kk][half * 66 + ty * 8];
#pragma unroll
            for (int i = 0; i < 8; i++) {
                float av = ap[i];
#pragma unroll
                for (int j = 0; j < 4; j++) acc[i][j] += av * brr[j];
            }
        }
        __syncthreads();
    }

    const float* suff = g_suffV + ((half ? bh1 : bh0) * 17 + cidx) * HD;
    const float* csum = g_suffV + ((half ? bh1 : bh0) * 17 + 0) * HD;
    const float* rc0 = g_rowconst + bh0 * S;
    const float* rc1 = g_rowconst + bh1 * S;
    const float mb = half ? mb1 : mb0;
    const float ma = half ? m10 : m00;
    const float mbx = half ? m11 : m01;
    __nv_bfloat16* Oh = g_aoh + (size_t)b * S * E + h0 * HD;
    __nv_bfloat16* Ol = g_aol + (size_t)b * S * E + h0 * HD;

#pragma unroll
    for (int i = 0; i < 8; i++) {
        int q = Q0 + ty * 8 + i;
        float cmix = ma * rc0[q] + mbx * rc1[q];
#pragma unroll
        for (int j = 0; j < 4; j++) {
            int dc = dcol + j;
            int d = dc & 63;
            float v = acc[i][j] + cmix * suff[d] + mb * csum[d];
            v = tanhf(alpha * v) * dyt_w[d] + dyt_b[d];
            v *= ds;
            __nv_bfloat16 vh = __float2bfloat16(v);
            Oh[(size_t)q * E + dc] = vh;
            Ol[(size_t)q * E + dc] = __float2bfloat16(v - __bfloat162float(vh));
        }
    }
}

// ============================================================================
// Launch
// ============================================================================
extern "C" void kernel_launch(void* const* d_in, const int* in_sizes, int n_in,
                              void* d_out, int out_size)
{
    const float* Q   = (const float*)d_in[0];
    const float* K   = (const float*)d_in[1];
    const float* V   = (const float*)d_in[2];
    const float* Wq  = (const float*)d_in[3];
    const float* bq  = (const float*)d_in[4];
    const float* Wk  = (const float*)d_in[5];
    const float* bk  = (const float*)d_in[6];
    const float* Wv  = (const float*)d_in[7];
    const float* bv  = (const float*)d_in[8];
    const float* Wo  = (const float*)d_in[9];
    const float* bo  = (const float*)d_in[10];
    const float* kq_w = (const float*)d_in[11];
    const float* kq_b = (const float*)d_in[12];
    const float* mix_w = (const float*)d_in[13];
    const float* mix_b = (const float*)d_in[14];
    const float* dyt_alpha = (const float*)d_in[15];
    const float* dyt_w = (const float*)d_in[16];
    const float* dyt_b = (const float*)d_in[17];
    const float* depth_scale = (const float*)d_in[18];

    cudaFuncSetAttribute(gemm_qkv_tc, cudaFuncAttributeMaxDynamicSharedMemorySize, GEMM_SMEM);
    cudaFuncSetAttribute(gemm_out_tc, cudaFuncAttributeMaxDynamicSharedMemorySize, GEMM_SMEM);

    asplit_kernel<<<dim3(2048, 1, 3), 256>>>(Q, K, V);
    wsplit_kernel<<<dim3(32, 32, 4), dim3(32, 8)>>>(Wq, Wk, Wv, Wo);
    gemm_qkv_tc<<<dim3(8, 16, 3), 256, GEMM_SMEM>>>(bq, bk, bv);
    suffv_kernel<<<BH, 256>>>();
    logits_kernel<<<dim3(36, BH), 256>>>();
    conv_softmax_kernel<<<dim3(S / QROWS, BH), 256>>>(kq_w, kq_b);
    pv_pair_kernel<<<dim3(1, S / 64, BH / 2), 256>>>(mix_w, mix_b, dyt_alpha, dyt_w, dyt_b, depth_scale);
    gemm_out_tc<<<dim3(8, 16), 256, GEMM_SMEM>>>(bo, (float*)d_out);
}

// round 5
// speedup vs baseline: 2.3474x; 1.2781x over previous
#include <cuda_runtime.h>
#include <cuda_bf16.h>
#include <math.h>
#include <cstdint>

#define S 1024
#define E 1024
#define H 16
#define HD 64
#define BATCH 2
#define BH (BATCH * H)     // 32
#define M_TOT (BATCH * S)  // 2048

// ---------------- scratch (device globals; no runtime allocation) ----------
__device__ __align__(16) float g_v[BH * S * HD];
__device__ __align__(16) float g_logits[BH * S * S];
__device__ __align__(16) float g_attn[BH * S * S];
__device__ __align__(16) float g_rowconst[BH * S];
__device__ __align__(16) float g_suffV[BH * 17 * HD];
__device__ __align__(16) __nv_bfloat16 g_ah[3 * M_TOT * E];
__device__ __align__(16) __nv_bfloat16 g_al[3 * M_TOT * E];
__device__ __align__(16) __nv_bfloat16 g_wth[4 * E * E];   // W^T [n][k]
__device__ __align__(16) __nv_bfloat16 g_wtl[4 * E * E];
__device__ __align__(16) __nv_bfloat16 g_aoh[M_TOT * E];
__device__ __align__(16) __nv_bfloat16 g_aol[M_TOT * E];
__device__ __align__(16) __nv_bfloat16 g_pjh[2 * BH * S * HD];  // q,k hi [bh][s][d]
__device__ __align__(16) __nv_bfloat16 g_pjl[2 * BH * S * HD];  // q,k lo

// ============================ PTX helpers ===================================
__device__ __forceinline__ uint32_t smem_u32(const void* p) {
    uint32_t a;
    asm("{ .reg .u64 t; cvta.to.shared.u64 t, %1; cvt.u32.u64 %0, t; }" : "=r"(a) : "l"(p));
    return a;
}
__device__ __forceinline__ void ldsm_x4(uint32_t* r, uint32_t addr) {
    asm volatile("ldmatrix.sync.aligned.m8n8.x4.shared.b16 {%0,%1,%2,%3}, [%4];"
        : "=r"(r[0]), "=r"(r[1]), "=r"(r[2]), "=r"(r[3]) : "r"(addr));
}
__device__ __forceinline__ void mma_bf16(float* c, const uint32_t* a, const uint32_t* b) {
    asm volatile("mma.sync.aligned.m16n8k16.row.col.f32.bf16.bf16.f32 "
        "{%0,%1,%2,%3}, {%4,%5,%6,%7}, {%8,%9}, {%0,%1,%2,%3};"
        : "+f"(c[0]), "+f"(c[1]), "+f"(c[2]), "+f"(c[3])
        : "r"(a[0]), "r"(a[1]), "r"(a[2]), "r"(a[3]), "r"(b[0]), "r"(b[1]));
}
__device__ __forceinline__ void cp16(uint32_t saddr, const void* g) {
    asm volatile("cp.async.cg.shared.global [%0], [%1], 16;" :: "r"(saddr), "l"(g));
}

// GEMM geometry: 128x128 block, BK=32, 8 warps (4m x 2n), warp 32x64.
#define PITCH 40                 // bf16 per smem row (80 B: conflict-free ldmatrix)
#define TILE_B 10240             // 128 * PITCH * 2
#define STAGE_B 40960            // 4 tiles (Ah, Al, Bh, Bl)
#define GEMM_SMEM (2 * STAGE_B)  // 81920

// ============================================================================
// prep: split f32 -> bf16 hi/lo (Q, K, V inputs)
// ============================================================================
__global__ __launch_bounds__(256) void asplit_kernel(
    const float* __restrict__ Q, const float* __restrict__ K, const float* __restrict__ V)
{
    int z = blockIdx.z;
    const float* X = (z == 0) ? Q : (z == 1) ? K : V;
    __nv_bfloat16* hp = g_ah + (size_t)z * M_TOT * E;
    __nv_bfloat16* lp = g_al + (size_t)z * M_TOT * E;
    int i = (blockIdx.x * 256 + threadIdx.x) * 4;
    float4 v = *(const float4*)(X + i);
    float vv[4] = {v.x, v.y, v.z, v.w};
#pragma unroll
    for (int j = 0; j < 4; j++) {
        __nv_bfloat16 h = __float2bfloat16(vv[j]);
        hp[i + j] = h;
        lp[i + j] = __float2bfloat16(vv[j] - __bfloat162float(h));
    }
}

// ============================================================================
// prep: transpose + split weights: Wt[n][k] = W[k][n], bf16 hi/lo
// ============================================================================
__global__ void wsplit_kernel(const float* __restrict__ Wq, const float* __restrict__ Wk,
                              const float* __restrict__ Wv, const float* __restrict__ Wo)
{
    int z = blockIdx.z;
    const float* W = (z == 0) ? Wq : (z == 1) ? Wk : (z == 2) ? Wv : Wo;
    __nv_bfloat16* th = g_wth + (size_t)z * E * E;
    __nv_bfloat16* tl = g_wtl + (size_t)z * E * E;
    __shared__ float tile[32][33];
    int n0 = blockIdx.x * 32, k0 = blockIdx.y * 32;
    int tx = threadIdx.x, ty = threadIdx.y;
    for (int i = ty; i < 32; i += 8)
        tile[i][tx] = W[(size_t)(k0 + i) * E + n0 + tx];
    __syncthreads();
    for (int i = ty; i < 32; i += 8) {
        float v = tile[tx][i];  // W[k0+tx][n0+i]
        __nv_bfloat16 h = __float2bfloat16(v);
        th[(size_t)(n0 + i) * E + k0 + tx] = h;
        tl[(size_t)(n0 + i) * E + k0 + tx] = __float2bfloat16(v - __bfloat162float(h));
    }
}

// ============================================================================
// mma.sync GEMM core (E-deep, pipelined)
// ============================================================================
__device__ __forceinline__ void gemm_load_stage(uint32_t sbs,
    const __nv_bfloat16* __restrict__ Ah, const __nv_bfloat16* __restrict__ Al,
    const __nv_bfloat16* __restrict__ Bh, const __nv_bfloat16* __restrict__ Bl,
    int m0, int n0, int k0)
{
    int t = threadIdx.x;
#pragma unroll
    for (int i = 0; i < 2; i++) {
        int idx = t + i * 256;
        int r = idx >> 2, c = (idx & 3) * 8;
        uint32_t so = (uint32_t)(r * PITCH + c) * 2;
        cp16(sbs + so,              Ah + (size_t)(m0 + r) * E + k0 + c);
        cp16(sbs + TILE_B + so,     Al + (size_t)(m0 + r) * E + k0 + c);
        cp16(sbs + 2 * TILE_B + so, Bh + (size_t)(n0 + r) * E + k0 + c);
        cp16(sbs + 3 * TILE_B + so, Bl + (size_t)(n0 + r) * E + k0 + c);
    }
}

__device__ __forceinline__ void gemm_compute_stage(
    uint32_t sb, int wm, int wn, int a_r, int a_c8, int b_r, int b_c8,
    float cacc[2][8][4])
{
#pragma unroll
    for (int kk = 0; kk < 32; kk += 16) {
        uint32_t ah[2][4], al[2][4], bh[4][4], bl[4][4];
#pragma unroll
        for (int mt = 0; mt < 2; mt++) {
            uint32_t ro = (uint32_t)((wm * 32 + mt * 16 + a_r) * PITCH + kk + a_c8) * 2;
            ldsm_x4(ah[mt], sb + ro);
            ldsm_x4(al[mt], sb + TILE_B + ro);
        }
#pragma unroll
        for (int i = 0; i < 4; i++) {
            uint32_t ro = (uint32_t)((wn * 64 + i * 16 + b_r) * PITCH + kk + b_c8) * 2;
            ldsm_x4(bh[i], sb + 2 * TILE_B + ro);
            ldsm_x4(bl[i], sb + 3 * TILE_B + ro);
        }
#pragma unroll
        for (int mt = 0; mt < 2; mt++)
#pragma unroll
            for (int nt = 0; nt < 8; nt++) {
                const uint32_t* bp  = &bh[nt >> 1][(nt & 1) * 2];
                const uint32_t* blp = &bl[nt >> 1][(nt & 1) * 2];
                mma_bf16(cacc[mt][nt], ah[mt], bp);
                mma_bf16(cacc[mt][nt], al[mt], bp);
                mma_bf16(cacc[mt][nt], ah[mt], blp);
            }
    }
}

__device__ __forceinline__ void gemm_mainloop(uint32_t sb,
    const __nv_bfloat16* Ah, const __nv_bfloat16* Al,
    const __nv_bfloat16* Bh, const __nv_bfloat16* Bl,
    int m0, int n0, int wm, int wn, int a_r, int a_c8, int b_r, int b_c8,
    float cacc[2][8][4])
{
    gemm_load_stage(sb, Ah, Al, Bh, Bl, m0, n0, 0);
    asm volatile("cp.async.commit_group;" ::: "memory");
    for (int c = 0; c < 32; c++) {
        if (c + 1 < 32) {
            gemm_load_stage(sb + ((c + 1) & 1) * STAGE_B, Ah, Al, Bh, Bl, m0, n0, (c + 1) * 32);
            asm volatile("cp.async.commit_group;" ::: "memory");
            asm volatile("cp.async.wait_group 1;" ::: "memory");
        } else {
            asm volatile("cp.async.wait_group 0;" ::: "memory");
        }
        __syncthreads();
        gemm_compute_stage(sb + (c & 1) * STAGE_B, wm, wn, a_r, a_c8, b_r, b_c8, cacc);
        __syncthreads();
    }
}

// ============================================================================
// GEMM kernel A: QKV projections. z<2 -> bf16 hi/lo splits; z==2 -> f32 g_v
// ============================================================================
__global__ void __launch_bounds__(256, 2) gemm_qkv_tc(
    const float* __restrict__ bq, const float* __restrict__ bk, const float* __restrict__ bv)
{
    extern __shared__ __align__(16) char smem[];
    uint32_t sb = smem_u32(smem);
    int z = blockIdx.z;
    int m0 = blockIdx.y * 128, n0 = blockIdx.x * 128;
    const __nv_bfloat16* Ah = g_ah + (size_t)z * M_TOT * E;
    const __nv_bfloat16* Al = g_al + (size_t)z * M_TOT * E;
    const __nv_bfloat16* Bh = g_wth + (size_t)z * E * E;
    const __nv_bfloat16* Bl = g_wtl + (size_t)z * E * E;
    const float* bias = (z == 0) ? bq : (z == 1) ? bk : bv;

    int lane = threadIdx.x & 31, wid = threadIdx.x >> 5;
    int wm = wid & 3, wn = wid >> 2;
    int a_r = lane & 15, a_c8 = (lane >> 4) * 8;
    int b_r = (lane & 7) | ((lane >> 4) << 3), b_c8 = ((lane >> 3) & 1) * 8;

    float cacc[2][8][4] = {};
    gemm_mainloop(sb, Ah, Al, Bh, Bl, m0, n0, wm, wn, a_r, a_c8, b_r, b_c8, cacc);

    if (z == 2) {
#pragma unroll
        for (int mt = 0; mt < 2; mt++)
#pragma unroll
            for (int nt = 0; nt < 8; nt++) {
                int m = m0 + wm * 32 + mt * 16 + (lane >> 2);
                int n = n0 + wn * 64 + nt * 8 + (lane & 3) * 2;
                int bb = m >> 10, s = m & 1023, h = n >> 6, d = n & 63;
                float* op = g_v + (((size_t)bb * H + h) * S + s) * HD + d;
                float b0 = bias[n], b1 = bias[n + 1];
                *(float2*)op = make_float2(cacc[mt][nt][0] + b0, cacc[mt][nt][1] + b1);
                *(float2*)(op + 8 * HD) = make_float2(cacc[mt][nt][2] + b0, cacc[mt][nt][3] + b1);
            }
    } else {
        __nv_bfloat16* ph = g_pjh + (size_t)z * (BH * S * HD);
        __nv_bfloat16* pl = g_pjl + (size_t)z * (BH * S * HD);
#pragma unroll
        for (int mt = 0; mt < 2; mt++)
#pragma unroll
            for (int nt = 0; nt < 8; nt++) {
                int m = m0 + wm * 32 + mt * 16 + (lane >> 2);
                int n = n0 + wn * 64 + nt * 8 + (lane & 3) * 2;
                int bb = m >> 10, s = m & 1023, h = n >> 6, d = n & 63;
                size_t base = (((size_t)bb * H + h) * S + s) * HD + d;
                float b0 = bias[n], b1 = bias[n + 1];
                float x0 = cacc[mt][nt][0] + b0, x1 = cacc[mt][nt][1] + b1;
                float x2 = cacc[mt][nt][2] + b0, x3 = cacc[mt][nt][3] + b1;
                __nv_bfloat16 h0 = __float2bfloat16(x0), h1 = __float2bfloat16(x1);
                __nv_bfloat16 h2 = __float2bfloat16(x2), h3 = __float2bfloat16(x3);
                *(__nv_bfloat162*)(ph + base) = __halves2bfloat162(h0, h1);
                *(__nv_bfloat162*)(ph + base + 8 * HD) = __halves2bfloat162(h2, h3);
                *(__nv_bfloat162*)(pl + base) = __halves2bfloat162(
                    __float2bfloat16(x0 - __bfloat162float(h0)),
                    __float2bfloat16(x1 - __bfloat162float(h1)));
                *(__nv_bfloat162*)(pl + base + 8 * HD) = __halves2bfloat162(
                    __float2bfloat16(x2 - __bfloat162float(h2)),
                    __float2bfloat16(x3 - __bfloat162float(h3)));
            }
    }
}

// ============================================================================
// GEMM kernel B: output projection -> d_out = AO @ Wo + bo
// ============================================================================
__global__ void __launch_bounds__(256, 2) gemm_out_tc(
    const float* __restrict__ bo, float* __restrict__ dout)
{
    extern __shared__ __align__(16) char smem[];
    uint32_t sb = smem_u32(smem);
    int m0 = blockIdx.y * 128, n0 = blockIdx.x * 128;
    const __nv_bfloat16* Bh = g_wth + (size_t)3 * E * E;
    const __nv_bfloat16* Bl = g_wtl + (size_t)3 * E * E;

    int lane = threadIdx.x & 31, wid = threadIdx.x >> 5;
    int wm = wid & 3, wn = wid >> 2;
    int a_r = lane & 15, a_c8 = (lane >> 4) * 8;
    int b_r = (lane & 7) | ((lane >> 4) << 3), b_c8 = ((lane >> 3) & 1) * 8;

    float cacc[2][8][4] = {};
    gemm_mainloop(sb, g_aoh, g_aol, Bh, Bl, m0, n0, wm, wn, a_r, a_c8, b_r, b_c8, cacc);

#pragma unroll
    for (int mt = 0; mt < 2; mt++)
#pragma unroll
        for (int nt = 0; nt < 8; nt++) {
            int m = m0 + wm * 32 + mt * 16 + (lane >> 2);
            int n = n0 + wn * 64 + nt * 8 + (lane & 3) * 2;
            float* op = dout + (size_t)m * E + n;
            float b0 = bo[n], b1 = bo[n + 1];
            *(float2*)op = make_float2(cacc[mt][nt][0] + b0, cacc[mt][nt][1] + b1);
            *(float2*)(op + 8 * E) = make_float2(cacc[mt][nt][2] + b0, cacc[mt][nt][3] + b1);
        }
}

// ============================================================================
// logits via mma (lower-tri tiles): L = (qh+ql)@(kh+kl)^T * 0.125, causal-mul
// ============================================================================
#define LPITCH 72
#define LTILE_B (128 * LPITCH * 2)   // 18432
#define LOG_SMEM (4 * LTILE_B)       // 73728

__global__ void __launch_bounds__(256, 2) logits_mma_kernel()
{
    extern __shared__ __align__(16) char smem[];
    uint32_t sb = smem_u32(smem);
    const int bh = blockIdx.y;
    int t = blockIdx.x, r = 0;
    while (t > r) { t -= r + 1; r++; }
    const int row0 = r * 128;
    const int col0 = t * 128;

    const __nv_bfloat16* Qh = g_pjh + (size_t)bh * S * HD;
    const __nv_bfloat16* Ql = g_pjl + (size_t)bh * S * HD;
    const __nv_bfloat16* Kh = g_pjh + (size_t)(BH + bh) * S * HD;
    const __nv_bfloat16* Kl = g_pjl + (size_t)(BH + bh) * S * HD;
    float* L = g_logits + (size_t)bh * S * S;

    int tid = threadIdx.x, lane = tid & 31, wid = tid >> 5;
    int wm = wid & 3, wn = wid >> 2;
    int a_r = lane & 15, a_c8 = (lane >> 4) * 8;
    int b_r = (lane & 7) | ((lane >> 4) << 3), b_c8 = ((lane >> 3) & 1) * 8;

    // load 4 tiles (qh, ql, kh, kl), each 128 x 64 bf16
#pragma unroll
    for (int i = 0; i < 4; i++) {
        int idx = tid + i * 256;
        int rr = idx >> 3, cc = (idx & 7) * 8;
        uint32_t so = (uint32_t)(rr * LPITCH + cc) * 2;
        cp16(sb + so,               Qh + (size_t)(row0 + rr) * HD + cc);
        cp16(sb + LTILE_B + so,     Ql + (size_t)(row0 + rr) * HD + cc);
        cp16(sb + 2 * LTILE_B + so, Kh + (size_t)(col0 + rr) * HD + cc);
        cp16(sb + 3 * LTILE_B + so, Kl + (size_t)(col0 + rr) * HD + cc);
    }
    asm volatile("cp.async.commit_group;" ::: "memory");
    asm volatile("cp.async.wait_group 0;" ::: "memory");
    __syncthreads();

    float cacc[2][8][4] = {};
#pragma unroll
    for (int kk = 0; kk < 64; kk += 16) {
        uint32_t ah[2][4], al[2][4], bhf[4][4], blf[4][4];
#pragma unroll
        for (int mt = 0; mt < 2; mt++) {
            uint32_t ro = (uint32_t)((wm * 32 + mt * 16 + a_r) * LPITCH + kk + a_c8) * 2;
            ldsm_x4(ah[mt], sb + ro);
            ldsm_x4(al[mt], sb + LTILE_B + ro);
        }
#pragma unroll
        for (int i = 0; i < 4; i++) {
            uint32_t ro = (uint32_t)((wn * 64 + i * 16 + b_r) * LPITCH + kk + b_c8) * 2;
            ldsm_x4(bhf[i], sb + 2 * LTILE_B + ro);
            ldsm_x4(blf[i], sb + 3 * LTILE_B + ro);
        }
#pragma unroll
        for (int mt = 0; mt < 2; mt++)
#pragma unroll
            for (int nt = 0; nt < 8; nt++) {
                const uint32_t* bp  = &bhf[nt >> 1][(nt & 1) * 2];
                const uint32_t* blp = &blf[nt >> 1][(nt & 1) * 2];
                mma_bf16(cacc[mt][nt], ah[mt], bp);
                mma_bf16(cacc[mt][nt], al[mt], bp);
                mma_bf16(cacc[mt][nt], ah[mt], blp);
            }
    }

    const float scale = 0.125f;
#pragma unroll
    for (int mt = 0; mt < 2; mt++)
#pragma unroll
        for (int nt = 0; nt < 8; nt++) {
            int m = row0 + wm * 32 + mt * 16 + (lane >> 2);
            int n = col0 + wn * 64 + nt * 8 + (lane & 3) * 2;
            float2 v0, v1;
            v0.x = (n     <= m) ? cacc[mt][nt][0] * scale : 0.f;
            v0.y = (n + 1 <= m) ? cacc[mt][nt][1] * scale : 0.f;
            v1.x = (n     <= m + 8) ? cacc[mt][nt][2] * scale : 0.f;
            v1.y = (n + 1 <= m + 8) ? cacc[mt][nt][3] * scale : 0.f;
            *(float2*)&L[(size_t)m * S + n] = v0;
            *(float2*)&L[(size_t)(m + 8) * S + n] = v1;
        }
}

// ============================================================================
// conv + analytic-constant softmax (register-rotation, gmem-direct)
// ============================================================================
__device__ __forceinline__ float block_reduce_max(float v) {
    __shared__ float sm[8];
    int lane = threadIdx.x & 31, wid = threadIdx.x >> 5;
#pragma unroll
    for (int o = 16; o; o >>= 1) v = fmaxf(v, __shfl_xor_sync(0xffffffffu, v, o));
    if (lane == 0) sm[wid] = v;
    __syncthreads();
    if (wid == 0) {
        v = sm[lane & 7];
#pragma unroll
        for (int o = 4; o; o >>= 1) v = fmaxf(v, __shfl_xor_sync(0xffffffffu, v, o));
        if (lane == 0) sm[0] = v;
    }
    __syncthreads();
    v = sm[0];
    __syncthreads();
    return v;
}
__device__ __forceinline__ float block_reduce_sum(float v) {
    __shared__ float ss[8];
    int lane = threadIdx.x & 31, wid = threadIdx.x >> 5;
#pragma unroll
    for (int o = 16; o; o >>= 1) v += __shfl_xor_sync(0xffffffffu, v, o);
    if (lane == 0) ss[wid] = v;
    __syncthreads();
    if (wid == 0) {
        v = ss[lane & 7];
#pragma unroll
        for (int o = 4; o; o >>= 1) v += __shfl_xor_sync(0xffffffffu, v, o);
        if (lane == 0) ss[0] = v;
    }
    __syncthreads();
    v = ss[0];
    __syncthreads();
    return v;
}

__device__ __forceinline__ void conv_load_row(const float* __restrict__ L, int qp, int c,
                                              int tid, float* sx, float* sw, float r[6])
{
    float4 v = make_float4(0.f, 0.f, 0.f, 0.f);
    if (qp >= 0 && c <= qp) {
        v = *(const float4*)&L[(size_t)qp * S + c];
        if (c + 1 > qp) v.y = 0.f;
        if (c + 2 > qp) v.z = 0.f;
        if (c + 3 > qp) v.w = 0.f;
    }
    __syncthreads();               // WAR: previous row's halo reads done
    sx[tid] = v.x; sw[tid] = v.w;
    __syncthreads();
    r[0] = (tid > 0) ? sw[tid - 1] : 0.f;
    r[1] = v.x; r[2] = v.y; r[3] = v.z; r[4] = v.w;
    r[5] = (tid < 255) ? sx[tid + 1] : 0.f;
}

#define QROWS 8
__global__ __launch_bounds__(256) void conv_softmax_kernel(
    const float* __restrict__ kq_w, const float* __restrict__ kq_b)
{
    const int bh = blockIdx.y;
    const int h  = bh & 15;
    const int q0 = blockIdx.x * QROWS;
    const float* L = g_logits + (size_t)bh * (S * S);
    float* A = g_attn + (size_t)bh * (S * S);

    __shared__ float sx[256], sw[256];
    const int tid = threadIdx.x;
    const int c = tid * 4;

    float wv[9];
#pragma unroll
    for (int t = 0; t < 9; t++) wv[t] = kq_w[h * 9 + t];
    const float bias = kq_b[h];

    float ra[6], rb[6], rc[6];
    conv_load_row(L, q0 - 2, c, tid, sx, sw, ra);
    conv_load_row(L, q0 - 1, c, tid, sx, sw, rb);

    for (int i = 0; i < QROWS; i++) {
        const int q = q0 + i;
        conv_load_row(L, q, c, tid, sx, sw, rc);
        const int kmax = (q + 1 <= S - 1) ? (q + 1) : (S - 1);

        float cv[4];
        float mxl = -1e30f;
#pragma unroll
        for (int u = 0; u < 4; u++) {
            int k = c + u;
            if (k <= kmax) {
                cv[u] = wv[0] * ra[u] + wv[1] * ra[u + 1] + wv[2] * ra[u + 2]
                      + wv[3] * rb[u] + wv[4] * rb[u + 1] + wv[5] * rb[u + 2]
                      + wv[6] * rc[u] + wv[7] * rc[u + 1] + wv[8] * rc[u + 2] + bias;
                mxl = fmaxf(mxl, cv[u]);
            } else cv[u] = 0.f;
        }
        float mx = fmaxf(block_reduce_max(mxl), bias);
        float e[4]; float esum = 0.f;
#pragma unroll
        for (int u = 0; u < 4; u++) {
            if (c + u <= kmax) { e[u] = __expf(cv[u] - mx); esum += e[u]; }
            else e[u] = 0.f;
        }
        int cnt = S - 2 - q; if (cnt < 0) cnt = 0;
        float eb = __expf(bias - mx);
        float sum = block_reduce_sum(esum) + (float)cnt * eb;
        float inv = 1.f / sum;
        float constv = eb * inv;

        int Klim = ((q >> 6) << 6) + 128; if (Klim > S) Klim = S;
        if (c < Klim) {
            float4 o;
            o.x = (c + 0 <= kmax) ? e[0] * inv : constv;
            o.y = (c + 1 <= kmax) ? e[1] * inv : constv;
            o.z = (c + 2 <= kmax) ? e[2] * inv : constv;
            o.w = (c + 3 <= kmax) ? e[3] * inv : constv;
            *(float4*)&A[(size_t)q * S + c] = o;
        }
        if (tid == 0) g_rowconst[bh * S + q] = constv;

        // rotate register rows
#pragma unroll
        for (int u = 0; u < 6; u++) { ra[u] = rb[u]; rb[u] = rc[u]; }
    }
}

// ============================================================================
// V chunk sums (grid BH x 16) + suffix scan (grid BH)
// ============================================================================
__global__ __launch_bounds__(256) void vchunk_kernel()
{
    const int bh = blockIdx.x, ci = blockIdx.y;
    const int tid = threadIdx.x;
    const int d = tid & 63, rg = tid >> 6;
    const float* V = g_v + (size_t)bh * S * HD;
    float s = 0.f;
#pragma unroll
    for (int r = 0; r < 16; r++)
        s += V[(ci * 64 + rg * 16 + r) * HD + d];
    __shared__ float sm[4][64];
    sm[rg][d] = s;
    __syncthreads();
    if (tid < 64)
        g_suffV[((size_t)bh * 17 + ci) * HD + tid] = sm[0][tid] + sm[1][tid] + sm[2][tid] + sm[3][tid];
}

__global__ void vscan_kernel()
{
    const int bh = blockIdx.x, d = threadIdx.x;
    g_suffV[((size_t)bh * 17 + 16) * HD + d] = 0.f;
    float suf = 0.f;
    for (int ci = 15; ci >= 0; ci--) {
        suf += g_suffV[((size_t)bh * 17 + ci) * HD + d];
        g_suffV[((size_t)bh * 17 + ci) * HD + d] = suf;
    }
}

// ============================================================================
// paired-head mix + attn@V (k < Klim) + constant-tail + DyT -> bf16 hi/lo
// ============================================================================
__global__ __launch_bounds__(256) void pv_pair_kernel(
    const float* __restrict__ mix_w, const float* __restrict__ mix_b,
    const float* __restrict__ dyt_alpha, const float* __restrict__ dyt_w,
    const float* __restrict__ dyt_b, const float* __restrict__ depth_scale)
{
    const int pair = blockIdx.z;
    const int b = pair >> 3, hp = pair & 7;
    const int h0 = hp * 2, h1 = h0 + 1;
    const int bh0 = b * 16 + h0, bh1 = bh0 + 1;
    const int Q0 = (gridDim.y - 1 - blockIdx.y) * 64;
    int Klim = Q0 + 128; if (Klim > S) Klim = S;
    const int cidx = Klim >> 6;

    const float* A0 = g_attn + (size_t)bh0 * (S * S);
    const float* A1 = g_attn + (size_t)bh1 * (S * S);
    const float* V0 = g_v + (size_t)bh0 * (S * HD);
    const float* V1 = g_v + (size_t)bh1 * (S * HD);

    const float m00 = mix_w[h0 * 2 + 0], m01 = mix_w[h0 * 2 + 1];
    const float m10 = mix_w[h1 * 2 + 0], m11 = mix_w[h1 * 2 + 1];
    const float mb0 = mix_b[h0], mb1 = mix_b[h1];
    const float alpha = dyt_alpha[0], ds = depth_scale[0];

    __shared__ float Am[16][132];
    __shared__ float Bv[16][128];

    const int tid = threadIdx.x;
    const int ar = tid >> 2, ac = (tid & 3) * 4;
    const int vr = tid >> 4, vc = (tid & 15) * 4;
    const int tx = tid & 31, ty = tid >> 5;
    const int dcol = tx * 4;
    const int half = (dcol >= 64) ? 1 : 0;

    float acc[8][4];
#pragma unroll
    for (int i = 0; i < 8; i++)
#pragma unroll
        for (int j = 0; j < 4; j++) acc[i][j] = 0.f;

    for (int k0 = 0; k0 < Klim; k0 += 16) {
        float4 a0 = *(const float4*)&A0[(size_t)(Q0 + ar) * S + k0 + ac];
        float4 a1 = *(const float4*)&A1[(size_t)(Q0 + ar) * S + k0 + ac];
        Am[ac + 0][ar] = m00 * a0.x + m01 * a1.x;
        Am[ac + 1][ar] = m00 * a0.y + m01 * a1.y;
        Am[ac + 2][ar] = m00 * a0.z + m01 * a1.z;
        Am[ac + 3][ar] = m00 * a0.w + m01 * a1.w;
        Am[ac + 0][66 + ar] = m10 * a0.x + m11 * a1.x;
        Am[ac + 1][66 + ar] = m10 * a0.y + m11 * a1.y;
        Am[ac + 2][66 + ar] = m10 * a0.z + m11 * a1.z;
        Am[ac + 3][66 + ar] = m10 * a0.w + m11 * a1.w;
        *(float4*)&Bv[vr][vc]      = *(const float4*)&V0[(k0 + vr) * HD + vc];
        *(float4*)&Bv[vr][64 + vc] = *(const float4*)&V1[(k0 + vr) * HD + vc];
        __syncthreads();
#pragma unroll
        for (int kk = 0; kk < 16; kk++) {
            float4 bv = *(const float4*)&Bv[kk][dcol];
            float brr[4] = {bv.x, bv.y, bv.z, bv.w};
            const float* ap = &Am[kk][half * 66 + ty * 8];
#pragma unroll
            for (int i = 0; i < 8; i++) {
                float av = ap[i];
#pragma unroll
                for (int j = 0; j < 4; j++) acc[i][j] += av * brr[j];
            }
        }
        __syncthreads();
    }

    const float* suff = g_suffV + ((size_t)(half ? bh1 : bh0) * 17 + cidx) * HD;
    const float* csum = g_suffV + ((size_t)(half ? bh1 : bh0) * 17 + 0) * HD;
    const float* rc0 = g_rowconst + bh0 * S;
    const float* rc1 = g_rowconst + bh1 * S;
    const float mb = half ? mb1 : mb0;
    const float ma = half ? m10 : m00;
    const float mbx = half ? m11 : m01;
    __nv_bfloat16* Oh = g_aoh + (size_t)b * S * E + h0 * HD;
    __nv_bfloat16* Ol = g_aol + (size_t)b * S * E + h0 * HD;

#pragma unroll
    for (int i = 0; i < 8; i++) {
        int q = Q0 + ty * 8 + i;
        float cmix = ma * rc0[q] + mbx * rc1[q];
#pragma unroll
        for (int j = 0; j < 4; j++) {
            int dc = dcol + j;
            int d = dc & 63;
            float v = acc[i][j] + cmix * suff[d] + mb * csum[d];
            v = tanhf(alpha * v) * dyt_w[d] + dyt_b[d];
            v *= ds;
            __nv_bfloat16 vh = __float2bfloat16(v);
            Oh[(size_t)q * E + dc] = vh;
            Ol[(size_t)q * E + dc] = __float2bfloat16(v - __bfloat162float(vh));
        }
    }
}

// ============================================================================
// Launch
// ============================================================================
extern "C" void kernel_launch(void* const* d_in, const int* in_sizes, int n_in,
                              void* d_out, int out_size)
{
    const float* Q   = (const float*)d_in[0];
    const float* K   = (const float*)d_in[1];
    const float* V   = (const float*)d_in[2];
    const float* Wq  = (const float*)d_in[3];
    const float* bq  = (const float*)d_in[4];
    const float* Wk  = (const float*)d_in[5];
    const float* bk  = (const float*)d_in[6];
    const float* Wv  = (const float*)d_in[7];
    const float* bv  = (const float*)d_in[8];
    const float* Wo  = (const float*)d_in[9];
    const float* bo  = (const float*)d_in[10];
    const float* kq_w = (const float*)d_in[11];
    const float* kq_b = (const float*)d_in[12];
    const float* mix_w = (const float*)d_in[13];
    const float* mix_b = (const float*)d_in[14];
    const float* dyt_alpha = (const float*)d_in[15];
    const float* dyt_w = (const float*)d_in[16];
    const float* dyt_b = (const float*)d_in[17];
    const float* depth_scale = (const float*)d_in[18];

    cudaFuncSetAttribute(gemm_qkv_tc, cudaFuncAttributeMaxDynamicSharedMemorySize, GEMM_SMEM);
    cudaFuncSetAttribute(gemm_out_tc, cudaFuncAttributeMaxDynamicSharedMemorySize, GEMM_SMEM);
    cudaFuncSetAttribute(logits_mma_kernel, cudaFuncAttributeMaxDynamicSharedMemorySize, LOG_SMEM);

    asplit_kernel<<<dim3(2048, 1, 3), 256>>>(Q, K, V);
    wsplit_kernel<<<dim3(32, 32, 4), dim3(32, 8)>>>(Wq, Wk, Wv, Wo);
    gemm_qkv_tc<<<dim3(8, 16, 3), 256, GEMM_SMEM>>>(bq, bk, bv);
    vchunk_kernel<<<dim3(BH, 16), 256>>>();
    vscan_kernel<<<BH, 64>>>();
    logits_mma_kernel<<<dim3(36, BH), 256, LOG_SMEM>>>();
    conv_softmax_kernel<<<dim3(S / QROWS, BH), 256>>>(kq_w, kq_b);
    pv_pair_kernel<<<dim3(1, S / 64, BH / 2), 256>>>(mix_w, mix_b, dyt_alpha, dyt_w, dyt_b, depth_scale);
    gemm_out_tc<<<dim3(8, 16), 256, GEMM_SMEM>>>(bo, (float*)d_out);
}

// round 6
// speedup vs baseline: 2.6685x; 1.1368x over previous
#include <cuda_runtime.h>
#include <cuda_bf16.h>
#include <math.h>
#include <cstdint>

#define S 1024
#define E 1024
#define H 16
#define HD 64
#define BATCH 2
#define BH (BATCH * H)     // 32
#define M_TOT (BATCH * S)  // 2048

// ---------------- scratch (device globals; no runtime allocation) ----------
__device__ __align__(16) float g_v[BH * S * HD];
__device__ __align__(16) float g_logits[BH * S * S];
__device__ __align__(16) float g_attn[BH * S * S];
__device__ __align__(16) float g_rowconst[BH * S];
__device__ __align__(16) float g_suffV[BH * 17 * HD];
__device__ __align__(16) __nv_bfloat16 g_ah[3 * M_TOT * E];
__device__ __align__(16) __nv_bfloat16 g_al[3 * M_TOT * E];
__device__ __align__(16) __nv_bfloat16 g_wth[4 * E * E];   // W^T [n][k]
__device__ __align__(16) __nv_bfloat16 g_wtl[4 * E * E];
__device__ __align__(16) __nv_bfloat16 g_aoh[M_TOT * E];
__device__ __align__(16) __nv_bfloat16 g_aol[M_TOT * E];
__device__ __align__(16) __nv_bfloat16 g_pjh[2 * BH * S * HD];  // q,k hi
__device__ __align__(16) __nv_bfloat16 g_pjl[2 * BH * S * HD];  // q,k lo
__device__ __align__(16) __nv_bfloat16 g_vbh[BH * S * HD];      // V hi
__device__ __align__(16) __nv_bfloat16 g_vbl[BH * S * HD];      // V lo

// ============================ PTX helpers ===================================
__device__ __forceinline__ uint32_t smem_u32(const void* p) {
    uint32_t a;
    asm("{ .reg .u64 t; cvta.to.shared.u64 t, %1; cvt.u32.u64 %0, t; }" : "=r"(a) : "l"(p));
    return a;
}
__device__ __forceinline__ void ldsm_x4(uint32_t* r, uint32_t addr) {
    asm volatile("ldmatrix.sync.aligned.m8n8.x4.shared.b16 {%0,%1,%2,%3}, [%4];"
        : "=r"(r[0]), "=r"(r[1]), "=r"(r[2]), "=r"(r[3]) : "r"(addr));
}
__device__ __forceinline__ void ldsm_x4_t(uint32_t* r, uint32_t addr) {
    asm volatile("ldmatrix.sync.aligned.m8n8.x4.trans.shared.b16 {%0,%1,%2,%3}, [%4];"
        : "=r"(r[0]), "=r"(r[1]), "=r"(r[2]), "=r"(r[3]) : "r"(addr));
}
__device__ __forceinline__ void mma_bf16(float* c, const uint32_t* a, const uint32_t* b) {
    asm volatile("mma.sync.aligned.m16n8k16.row.col.f32.bf16.bf16.f32 "
        "{%0,%1,%2,%3}, {%4,%5,%6,%7}, {%8,%9}, {%0,%1,%2,%3};"
        : "+f"(c[0]), "+f"(c[1]), "+f"(c[2]), "+f"(c[3])
        : "r"(a[0]), "r"(a[1]), "r"(a[2]), "r"(a[3]), "r"(b[0]), "r"(b[1]));
}
__device__ __forceinline__ void cp16(uint32_t saddr, const void* g) {
    asm volatile("cp.async.cg.shared.global [%0], [%1], 16;" :: "r"(saddr), "l"(g));
}
__device__ __forceinline__ void split_store4(__nv_bfloat16* hp, __nv_bfloat16* lp, const float* x) {
    __nv_bfloat16 h0 = __float2bfloat16(x[0]), h1 = __float2bfloat16(x[1]);
    __nv_bfloat16 h2 = __float2bfloat16(x[2]), h3 = __float2bfloat16(x[3]);
    *(__nv_bfloat162*)hp = __halves2bfloat162(h0, h1);
    *(__nv_bfloat162*)(hp + 2) = __halves2bfloat162(h2, h3);
    *(__nv_bfloat162*)lp = __halves2bfloat162(
        __float2bfloat16(x[0] - __bfloat162float(h0)),
        __float2bfloat16(x[1] - __bfloat162float(h1)));
    *(__nv_bfloat162*)(lp + 2) = __halves2bfloat162(
        __float2bfloat16(x[2] - __bfloat162float(h2)),
        __float2bfloat16(x[3] - __bfloat162float(h3)));
}

// GEMM geometry: 128x128 block, BK=32, 8 warps (4m x 2n), warp 32x64.
#define PITCH 40                 // bf16 per smem row (80 B: conflict-free ldmatrix)
#define TILE_B 10240             // 128 * PITCH * 2
#define STAGE_B 40960            // 4 tiles (Ah, Al, Bh, Bl)
#define GEMM_SMEM (2 * STAGE_B)  // 81920

// ============================================================================
// prep: split f32 -> bf16 hi/lo (Q, K, V inputs)
// ============================================================================
__global__ __launch_bounds__(256) void asplit_kernel(
    const float* __restrict__ Q, const float* __restrict__ K, const float* __restrict__ V)
{
    int z = blockIdx.z;
    const float* X = (z == 0) ? Q : (z == 1) ? K : V;
    __nv_bfloat16* hp = g_ah + (size_t)z * M_TOT * E;
    __nv_bfloat16* lp = g_al + (size_t)z * M_TOT * E;
    int i = (blockIdx.x * 256 + threadIdx.x) * 4;
    float4 v = *(const float4*)(X + i);
    float vv[4] = {v.x, v.y, v.z, v.w};
#pragma unroll
    for (int j = 0; j < 4; j++) {
        __nv_bfloat16 h = __float2bfloat16(vv[j]);
        hp[i + j] = h;
        lp[i + j] = __float2bfloat16(vv[j] - __bfloat162float(h));
    }
}

// ============================================================================
// prep: transpose + split weights: Wt[n][k] = W[k][n], bf16 hi/lo
// ============================================================================
__global__ void wsplit_kernel(const float* __restrict__ Wq, const float* __restrict__ Wk,
                              const float* __restrict__ Wv, const float* __restrict__ Wo)
{
    int z = blockIdx.z;
    const float* W = (z == 0) ? Wq : (z == 1) ? Wk : (z == 2) ? Wv : Wo;
    __nv_bfloat16* th = g_wth + (size_t)z * E * E;
    __nv_bfloat16* tl = g_wtl + (size_t)z * E * E;
    __shared__ float tile[32][33];
    int n0 = blockIdx.x * 32, k0 = blockIdx.y * 32;
    int tx = threadIdx.x, ty = threadIdx.y;
    for (int i = ty; i < 32; i += 8)
        tile[i][tx] = W[(size_t)(k0 + i) * E + n0 + tx];
    __syncthreads();
    for (int i = ty; i < 32; i += 8) {
        float v = tile[tx][i];
        __nv_bfloat16 h = __float2bfloat16(v);
        th[(size_t)(n0 + i) * E + k0 + tx] = h;
        tl[(size_t)(n0 + i) * E + k0 + tx] = __float2bfloat16(v - __bfloat162float(h));
    }
}

// ============================================================================
// mma.sync GEMM core (E-deep, pipelined)
// ============================================================================
__device__ __forceinline__ void gemm_load_stage(uint32_t sbs,
    const __nv_bfloat16* __restrict__ Ah, const __nv_bfloat16* __restrict__ Al,
    const __nv_bfloat16* __restrict__ Bh, const __nv_bfloat16* __restrict__ Bl,
    int m0, int n0, int k0)
{
    int t = threadIdx.x;
#pragma unroll
    for (int i = 0; i < 2; i++) {
        int idx = t + i * 256;
        int r = idx >> 2, c = (idx & 3) * 8;
        uint32_t so = (uint32_t)(r * PITCH + c) * 2;
        cp16(sbs + so,              Ah + (size_t)(m0 + r) * E + k0 + c);
        cp16(sbs + TILE_B + so,     Al + (size_t)(m0 + r) * E + k0 + c);
        cp16(sbs + 2 * TILE_B + so, Bh + (size_t)(n0 + r) * E + k0 + c);
        cp16(sbs + 3 * TILE_B + so, Bl + (size_t)(n0 + r) * E + k0 + c);
    }
}

__device__ __forceinline__ void gemm_compute_stage(
    uint32_t sb, int wm, int wn, int a_r, int a_c8, int b_r, int b_c8,
    float cacc[2][8][4])
{
#pragma unroll
    for (int kk = 0; kk < 32; kk += 16) {
        uint32_t ah[2][4], al[2][4], bh[4][4], bl[4][4];
#pragma unroll
        for (int mt = 0; mt < 2; mt++) {
            uint32_t ro = (uint32_t)((wm * 32 + mt * 16 + a_r) * PITCH + kk + a_c8) * 2;
            ldsm_x4(ah[mt], sb + ro);
            ldsm_x4(al[mt], sb + TILE_B + ro);
        }
#pragma unroll
        for (int i = 0; i < 4; i++) {
            uint32_t ro = (uint32_t)((wn * 64 + i * 16 + b_r) * PITCH + kk + b_c8) * 2;
            ldsm_x4(bh[i], sb + 2 * TILE_B + ro);
            ldsm_x4(bl[i], sb + 3 * TILE_B + ro);
        }
#pragma unroll
        for (int mt = 0; mt < 2; mt++)
#pragma unroll
            for (int nt = 0; nt < 8; nt++) {
                const uint32_t* bp  = &bh[nt >> 1][(nt & 1) * 2];
                const uint32_t* blp = &bl[nt >> 1][(nt & 1) * 2];
                mma_bf16(cacc[mt][nt], ah[mt], bp);
                mma_bf16(cacc[mt][nt], al[mt], bp);
                mma_bf16(cacc[mt][nt], ah[mt], blp);
            }
    }
}

__device__ __forceinline__ void gemm_mainloop(uint32_t sb,
    const __nv_bfloat16* Ah, const __nv_bfloat16* Al,
    const __nv_bfloat16* Bh, const __nv_bfloat16* Bl,
    int m0, int n0, int wm, int wn, int a_r, int a_c8, int b_r, int b_c8,
    float cacc[2][8][4])
{
    gemm_load_stage(sb, Ah, Al, Bh, Bl, m0, n0, 0);
    asm volatile("cp.async.commit_group;" ::: "memory");
    for (int c = 0; c < 32; c++) {
        if (c + 1 < 32) {
            gemm_load_stage(sb + ((c + 1) & 1) * STAGE_B, Ah, Al, Bh, Bl, m0, n0, (c + 1) * 32);
            asm volatile("cp.async.commit_group;" ::: "memory");
            asm volatile("cp.async.wait_group 1;" ::: "memory");
        } else {
            asm volatile("cp.async.wait_group 0;" ::: "memory");
        }
        __syncthreads();
        gemm_compute_stage(sb + (c & 1) * STAGE_B, wm, wn, a_r, a_c8, b_r, b_c8, cacc);
        __syncthreads();
    }
}

// ============================================================================
// GEMM kernel A: QKV projections. z<2 -> q/k bf16 splits; z==2 -> f32 V + splits
// ============================================================================
__global__ void __launch_bounds__(256, 2) gemm_qkv_tc(
    const float* __restrict__ bq, const float* __restrict__ bk, const float* __restrict__ bv)
{
    extern __shared__ __align__(16) char smem[];
    uint32_t sb = smem_u32(smem);
    int z = blockIdx.z;
    int m0 = blockIdx.y * 128, n0 = blockIdx.x * 128;
    const __nv_bfloat16* Ah = g_ah + (size_t)z * M_TOT * E;
    const __nv_bfloat16* Al = g_al + (size_t)z * M_TOT * E;
    const __nv_bfloat16* Bh = g_wth + (size_t)z * E * E;
    const __nv_bfloat16* Bl = g_wtl + (size_t)z * E * E;
    const float* bias = (z == 0) ? bq : (z == 1) ? bk : bv;

    int lane = threadIdx.x & 31, wid = threadIdx.x >> 5;
    int wm = wid & 3, wn = wid >> 2;
    int a_r = lane & 15, a_c8 = (lane >> 4) * 8;
    int b_r = (lane & 7) | ((lane >> 4) << 3), b_c8 = ((lane >> 3) & 1) * 8;

    float cacc[2][8][4] = {};
    gemm_mainloop(sb, Ah, Al, Bh, Bl, m0, n0, wm, wn, a_r, a_c8, b_r, b_c8, cacc);

    if (z == 2) {
#pragma unroll
        for (int mt = 0; mt < 2; mt++)
#pragma unroll
            for (int nt = 0; nt < 8; nt++) {
                int m = m0 + wm * 32 + mt * 16 + (lane >> 2);
                int n = n0 + wn * 64 + nt * 8 + (lane & 3) * 2;
                int bb = m >> 10, s = m & 1023, h = n >> 6, d = n & 63;
                size_t base = (((size_t)bb * H + h) * S + s) * HD + d;
                float b0 = bias[n], b1 = bias[n + 1];
                float x0 = cacc[mt][nt][0] + b0, x1 = cacc[mt][nt][1] + b1;
                float x2 = cacc[mt][nt][2] + b0, x3 = cacc[mt][nt][3] + b1;
                *(float2*)(g_v + base) = make_float2(x0, x1);
                *(float2*)(g_v + base + 8 * HD) = make_float2(x2, x3);
                __nv_bfloat16 h0 = __float2bfloat16(x0), h1 = __float2bfloat16(x1);
                __nv_bfloat16 h2 = __float2bfloat16(x2), h3 = __float2bfloat16(x3);
                *(__nv_bfloat162*)(g_vbh + base) = __halves2bfloat162(h0, h1);
                *(__nv_bfloat162*)(g_vbh + base + 8 * HD) = __halves2bfloat162(h2, h3);
                *(__nv_bfloat162*)(g_vbl + base) = __halves2bfloat162(
                    __float2bfloat16(x0 - __bfloat162float(h0)),
                    __float2bfloat16(x1 - __bfloat162float(h1)));
                *(__nv_bfloat162*)(g_vbl + base + 8 * HD) = __halves2bfloat162(
                    __float2bfloat16(x2 - __bfloat162float(h2)),
                    __float2bfloat16(x3 - __bfloat162float(h3)));
            }
    } else {
        __nv_bfloat16* ph = g_pjh + (size_t)z * (BH * S * HD);
        __nv_bfloat16* pl = g_pjl + (size_t)z * (BH * S * HD);
#pragma unroll
        for (int mt = 0; mt < 2; mt++)
#pragma unroll
            for (int nt = 0; nt < 8; nt++) {
                int m = m0 + wm * 32 + mt * 16 + (lane >> 2);
                int n = n0 + wn * 64 + nt * 8 + (lane & 3) * 2;
                int bb = m >> 10, s = m & 1023, h = n >> 6, d = n & 63;
                size_t base = (((size_t)bb * H + h) * S + s) * HD + d;
                float b0 = bias[n], b1 = bias[n + 1];
                float x0 = cacc[mt][nt][0] + b0, x1 = cacc[mt][nt][1] + b1;
                float x2 = cacc[mt][nt][2] + b0, x3 = cacc[mt][nt][3] + b1;
                __nv_bfloat16 h0 = __float2bfloat16(x0), h1 = __float2bfloat16(x1);
                __nv_bfloat16 h2 = __float2bfloat16(x2), h3 = __float2bfloat16(x3);
                *(__nv_bfloat162*)(ph + base) = __halves2bfloat162(h0, h1);
                *(__nv_bfloat162*)(ph + base + 8 * HD) = __halves2bfloat162(h2, h3);
                *(__nv_bfloat162*)(pl + base) = __halves2bfloat162(
                    __float2bfloat16(x0 - __bfloat162float(h0)),
                    __float2bfloat16(x1 - __bfloat162float(h1)));
                *(__nv_bfloat162*)(pl + base + 8 * HD) = __halves2bfloat162(
                    __float2bfloat16(x2 - __bfloat162float(h2)),
                    __float2bfloat16(x3 - __bfloat162float(h3)));
            }
    }
}

// ============================================================================
// GEMM kernel B: output projection -> d_out = AO @ Wo + bo
// ============================================================================
__global__ void __launch_bounds__(256, 2) gemm_out_tc(
    const float* __restrict__ bo, float* __restrict__ dout)
{
    extern __shared__ __align__(16) char smem[];
    uint32_t sb = smem_u32(smem);
    int m0 = blockIdx.y * 128, n0 = blockIdx.x * 128;
    const __nv_bfloat16* Bh = g_wth + (size_t)3 * E * E;
    const __nv_bfloat16* Bl = g_wtl + (size_t)3 * E * E;

    int lane = threadIdx.x & 31, wid = threadIdx.x >> 5;
    int wm = wid & 3, wn = wid >> 2;
    int a_r = lane & 15, a_c8 = (lane >> 4) * 8;
    int b_r = (lane & 7) | ((lane >> 4) << 3), b_c8 = ((lane >> 3) & 1) * 8;

    float cacc[2][8][4] = {};
    gemm_mainloop(sb, g_aoh, g_aol, Bh, Bl, m0, n0, wm, wn, a_r, a_c8, b_r, b_c8, cacc);

#pragma unroll
    for (int mt = 0; mt < 2; mt++)
#pragma unroll
        for (int nt = 0; nt < 8; nt++) {
            int m = m0 + wm * 32 + mt * 16 + (lane >> 2);
            int n = n0 + wn * 64 + nt * 8 + (lane & 3) * 2;
            float* op = dout + (size_t)m * E + n;
            float b0 = bo[n], b1 = bo[n + 1];
            *(float2*)op = make_float2(cacc[mt][nt][0] + b0, cacc[mt][nt][1] + b1);
            *(float2*)(op + 8 * E) = make_float2(cacc[mt][nt][2] + b0, cacc[mt][nt][3] + b1);
        }
}

// ============================================================================
// logits via mma (lower-tri tiles)
// ============================================================================
#define LPITCH 72
#define LTILE_B (128 * LPITCH * 2)   // 18432
#define LOG_SMEM (4 * LTILE_B)       // 73728

__global__ void __launch_bounds__(256, 2) logits_mma_kernel()
{
    extern __shared__ __align__(16) char smem[];
    uint32_t sb = smem_u32(smem);
    const int bh = blockIdx.y;
    int t = blockIdx.x, r = 0;
    while (t > r) { t -= r + 1; r++; }
    const int row0 = r * 128;
    const int col0 = t * 128;

    const __nv_bfloat16* Qh = g_pjh + (size_t)bh * S * HD;
    const __nv_bfloat16* Ql = g_pjl + (size_t)bh * S * HD;
    const __nv_bfloat16* Kh = g_pjh + (size_t)(BH + bh) * S * HD;
    const __nv_bfloat16* Kl = g_pjl + (size_t)(BH + bh) * S * HD;
    float* L = g_logits + (size_t)bh * S * S;

    int tid = threadIdx.x, lane = tid & 31, wid = tid >> 5;
    int wm = wid & 3, wn = wid >> 2;
    int a_r = lane & 15, a_c8 = (lane >> 4) * 8;
    int b_r = (lane & 7) | ((lane >> 4) << 3), b_c8 = ((lane >> 3) & 1) * 8;

#pragma unroll
    for (int i = 0; i < 4; i++) {
        int idx = tid + i * 256;
        int rr = idx >> 3, cc = (idx & 7) * 8;
        uint32_t so = (uint32_t)(rr * LPITCH + cc) * 2;
        cp16(sb + so,               Qh + (size_t)(row0 + rr) * HD + cc);
        cp16(sb + LTILE_B + so,     Ql + (size_t)(row0 + rr) * HD + cc);
        cp16(sb + 2 * LTILE_B + so, Kh + (size_t)(col0 + rr) * HD + cc);
        cp16(sb + 3 * LTILE_B + so, Kl + (size_t)(col0 + rr) * HD + cc);
    }
    asm volatile("cp.async.commit_group;" ::: "memory");
    asm volatile("cp.async.wait_group 0;" ::: "memory");
    __syncthreads();

    float cacc[2][8][4] = {};
#pragma unroll
    for (int kk = 0; kk < 64; kk += 16) {
        uint32_t ah[2][4], al[2][4], bhf[4][4], blf[4][4];
#pragma unroll
        for (int mt = 0; mt < 2; mt++) {
            uint32_t ro = (uint32_t)((wm * 32 + mt * 16 + a_r) * LPITCH + kk + a_c8) * 2;
            ldsm_x4(ah[mt], sb + ro);
            ldsm_x4(al[mt], sb + LTILE_B + ro);
        }
#pragma unroll
        for (int i = 0; i < 4; i++) {
            uint32_t ro = (uint32_t)((wn * 64 + i * 16 + b_r) * LPITCH + kk + b_c8) * 2;
            ldsm_x4(bhf[i], sb + 2 * LTILE_B + ro);
            ldsm_x4(blf[i], sb + 3 * LTILE_B + ro);
        }
#pragma unroll
        for (int mt = 0; mt < 2; mt++)
#pragma unroll
            for (int nt = 0; nt < 8; nt++) {
                const uint32_t* bp  = &bhf[nt >> 1][(nt & 1) * 2];
                const uint32_t* blp = &blf[nt >> 1][(nt & 1) * 2];
                mma_bf16(cacc[mt][nt], ah[mt], bp);
                mma_bf16(cacc[mt][nt], al[mt], bp);
                mma_bf16(cacc[mt][nt], ah[mt], blp);
            }
    }

    const float scale = 0.125f;
#pragma unroll
    for (int mt = 0; mt < 2; mt++)
#pragma unroll
        for (int nt = 0; nt < 8; nt++) {
            int m = row0 + wm * 32 + mt * 16 + (lane >> 2);
            int n = col0 + wn * 64 + nt * 8 + (lane & 3) * 2;
            float2 v0, v1;
            v0.x = (n     <= m) ? cacc[mt][nt][0] * scale : 0.f;
            v0.y = (n + 1 <= m) ? cacc[mt][nt][1] * scale : 0.f;
            v1.x = (n     <= m + 8) ? cacc[mt][nt][2] * scale : 0.f;
            v1.y = (n + 1 <= m + 8) ? cacc[mt][nt][3] * scale : 0.f;
            *(float2*)&L[(size_t)m * S + n] = v0;
            *(float2*)&L[(size_t)(m + 8) * S + n] = v1;
        }
}

// ============================================================================
// conv + analytic-constant softmax (register-rotation, gmem-direct)
// ============================================================================
__device__ __forceinline__ float block_reduce_max(float v) {
    __shared__ float sm[8];
    int lane = threadIdx.x & 31, wid = threadIdx.x >> 5;
#pragma unroll
    for (int o = 16; o; o >>= 1) v = fmaxf(v, __shfl_xor_sync(0xffffffffu, v, o));
    if (lane == 0) sm[wid] = v;
    __syncthreads();
    if (wid == 0) {
        v = sm[lane & 7];
#pragma unroll
        for (int o = 4; o; o >>= 1) v = fmaxf(v, __shfl_xor_sync(0xffffffffu, v, o));
        if (lane == 0) sm[0] = v;
    }
    __syncthreads();
    v = sm[0];
    __syncthreads();
    return v;
}
__device__ __forceinline__ float block_reduce_sum(float v) {
    __shared__ float ss[8];
    int lane = threadIdx.x & 31, wid = threadIdx.x >> 5;
#pragma unroll
    for (int o = 16; o; o >>= 1) v += __shfl_xor_sync(0xffffffffu, v, o);
    if (lane == 0) ss[wid] = v;
    __syncthreads();
    if (wid == 0) {
        v = ss[lane & 7];
#pragma unroll
        for (int o = 4; o; o >>= 1) v += __shfl_xor_sync(0xffffffffu, v, o);
        if (lane == 0) ss[0] = v;
    }
    __syncthreads();
    v = ss[0];
    __syncthreads();
    return v;
}

__device__ __forceinline__ void conv_load_row(const float* __restrict__ L, int qp, int c,
                                              int tid, float* sx, float* sw, float r[6])
{
    float4 v = make_float4(0.f, 0.f, 0.f, 0.f);
    if (qp >= 0 && c <= qp) {
        v = *(const float4*)&L[(size_t)qp * S + c];
        if (c + 1 > qp) v.y = 0.f;
        if (c + 2 > qp) v.z = 0.f;
        if (c + 3 > qp) v.w = 0.f;
    }
    __syncthreads();
    sx[tid] = v.x; sw[tid] = v.w;
    __syncthreads();
    r[0] = (tid > 0) ? sw[tid - 1] : 0.f;
    r[1] = v.x; r[2] = v.y; r[3] = v.z; r[4] = v.w;
    r[5] = (tid < 255) ? sx[tid + 1] : 0.f;
}

#define QROWS 8
__global__ __launch_bounds__(256) void conv_softmax_kernel(
    const float* __restrict__ kq_w, const float* __restrict__ kq_b)
{
    const int bh = blockIdx.y;
    const int h  = bh & 15;
    const int q0 = blockIdx.x * QROWS;
    const float* L = g_logits + (size_t)bh * (S * S);
    float* A = g_attn + (size_t)bh * (S * S);

    __shared__ float sx[256], sw[256];
    const int tid = threadIdx.x;
    const int c = tid * 4;

    float wv[9];
#pragma unroll
    for (int t = 0; t < 9; t++) wv[t] = kq_w[h * 9 + t];
    const float bias = kq_b[h];

    float ra[6], rb[6], rc[6];
    conv_load_row(L, q0 - 2, c, tid, sx, sw, ra);
    conv_load_row(L, q0 - 1, c, tid, sx, sw, rb);

    for (int i = 0; i < QROWS; i++) {
        const int q = q0 + i;
        conv_load_row(L, q, c, tid, sx, sw, rc);
        const int kmax = (q + 1 <= S - 1) ? (q + 1) : (S - 1);

        float cv[4];
        float mxl = -1e30f;
#pragma unroll
        for (int u = 0; u < 4; u++) {
            int k = c + u;
            if (k <= kmax) {
                cv[u] = wv[0] * ra[u] + wv[1] * ra[u + 1] + wv[2] * ra[u + 2]
                      + wv[3] * rb[u] + wv[4] * rb[u + 1] + wv[5] * rb[u + 2]
                      + wv[6] * rc[u] + wv[7] * rc[u + 1] + wv[8] * rc[u + 2] + bias;
                mxl = fmaxf(mxl, cv[u]);
            } else cv[u] = 0.f;
        }
        float mx = fmaxf(block_reduce_max(mxl), bias);
        float e[4]; float esum = 0.f;
#pragma unroll
        for (int u = 0; u < 4; u++) {
            if (c + u <= kmax) { e[u] = __expf(cv[u] - mx); esum += e[u]; }
            else e[u] = 0.f;
        }
        int cnt = S - 2 - q; if (cnt < 0) cnt = 0;
        float eb = __expf(bias - mx);
        float sum = block_reduce_sum(esum) + (float)cnt * eb;
        float inv = 1.f / sum;
        float constv = eb * inv;

        int Klim = ((q >> 6) << 6) + 128; if (Klim > S) Klim = S;
        if (c < Klim) {
            float4 o;
            o.x = (c + 0 <= kmax) ? e[0] * inv : constv;
            o.y = (c + 1 <= kmax) ? e[1] * inv : constv;
            o.z = (c + 2 <= kmax) ? e[2] * inv : constv;
            o.w = (c + 3 <= kmax) ? e[3] * inv : constv;
            *(float4*)&A[(size_t)q * S + c] = o;
        }
        if (tid == 0) g_rowconst[bh * S + q] = constv;

#pragma unroll
        for (int u = 0; u < 6; u++) { ra[u] = rb[u]; rb[u] = rc[u]; }
    }
}

// ============================================================================
// V chunk sums + suffix scan
// ============================================================================
__global__ __launch_bounds__(256) void vchunk_kernel()
{
    const int bh = blockIdx.x, ci = blockIdx.y;
    const int tid = threadIdx.x;
    const int d = tid & 63, rg = tid >> 6;
    const float* V = g_v + (size_t)bh * S * HD;
    float s = 0.f;
#pragma unroll
    for (int r = 0; r < 16; r++)
        s += V[(ci * 64 + rg * 16 + r) * HD + d];
    __shared__ float sm[4][64];
    sm[rg][d] = s;
    __syncthreads();
    if (tid < 64)
        g_suffV[((size_t)bh * 17 + ci) * HD + tid] = sm[0][tid] + sm[1][tid] + sm[2][tid] + sm[3][tid];
}

__global__ void vscan_kernel()
{
    const int bh = blockIdx.x, d = threadIdx.x;
    g_suffV[((size_t)bh * 17 + 16) * HD + d] = 0.f;
    float suf = 0.f;
    for (int ci = 15; ci >= 0; ci--) {
        suf += g_suffV[((size_t)bh * 17 + ci) * HD + d];
        g_suffV[((size_t)bh * 17 + ci) * HD + d] = suf;
    }
}

// ============================================================================
// pv via mma: out[64q x 128d(two heads)] = mix(attn) @ V  + tails + DyT
// ============================================================================
#define PV_APITCH 40
#define PV_VPITCH 136

__global__ __launch_bounds__(256) void pv_mma_kernel(
    const float* __restrict__ mix_w, const float* __restrict__ mix_b,
    const float* __restrict__ dyt_alpha, const float* __restrict__ dyt_w,
    const float* __restrict__ dyt_b, const float* __restrict__ depth_scale)
{
    const int pair = blockIdx.z;
    const int b = pair >> 3, hp = pair & 7;
    const int h0 = hp * 2, h1 = h0 + 1;
    const int bh0 = b * 16 + h0, bh1 = bh0 + 1;
    const int Q0 = (gridDim.y - 1 - blockIdx.y) * 64;
    int Klim = Q0 + 128; if (Klim > S) Klim = S;
    const int cidx = Klim >> 6;

    const float* A0 = g_attn + (size_t)bh0 * S * S;
    const float* A1 = g_attn + (size_t)bh1 * S * S;
    const __nv_bfloat16* V0h = g_vbh + (size_t)bh0 * S * HD;
    const __nv_bfloat16* V0l = g_vbl + (size_t)bh0 * S * HD;
    const __nv_bfloat16* V1h = g_vbh + (size_t)bh1 * S * HD;
    const __nv_bfloat16* V1l = g_vbl + (size_t)bh1 * S * HD;

    const float m00 = mix_w[h0 * 2 + 0], m01 = mix_w[h0 * 2 + 1];
    const float m10 = mix_w[h1 * 2 + 0], m11 = mix_w[h1 * 2 + 1];

    __shared__ __align__(16) __nv_bfloat16 sA[4][64 * PV_APITCH];  // [hh*2+split]
    __shared__ __align__(16) __nv_bfloat16 sV[2][32 * PV_VPITCH];  // [split][k][d]

    const int tid = threadIdx.x, lane = tid & 31, wid = tid >> 5;
    const int wm = wid & 3, wn = wid >> 2;
    const int a_r = lane & 15, a_c8 = (lane >> 4) * 8;
    const int bt_r = lane & 15, bt_c8 = (lane >> 4) * 8;

    const uint32_t sAh = smem_u32(&sA[wn * 2][0]);
    const uint32_t sAl = smem_u32(&sA[wn * 2 + 1][0]);
    const uint32_t sVh = smem_u32(&sV[0][0]);
    const uint32_t sVl = smem_u32(&sV[1][0]);

    float acc[8][4] = {};

    // V stage indices (fixed per thread)
    const int vrow = tid >> 3, vc8 = (tid & 7) * 8;

    for (int k0 = 0; k0 < Klim; k0 += 32) {
        // stage A: read attn f32 once, mix for both heads, split to bf16 hi/lo
#pragma unroll
        for (int i = 0; i < 2; i++) {
            int idx = tid + i * 256;
            int qr = idx >> 3, kc = (idx & 7) * 4;
            float4 a0 = *(const float4*)&A0[(size_t)(Q0 + qr) * S + k0 + kc];
            float4 a1 = *(const float4*)&A1[(size_t)(Q0 + qr) * S + k0 + kc];
            float x0[4] = {m00 * a0.x + m01 * a1.x, m00 * a0.y + m01 * a1.y,
                           m00 * a0.z + m01 * a1.z, m00 * a0.w + m01 * a1.w};
            float x1[4] = {m10 * a0.x + m11 * a1.x, m10 * a0.y + m11 * a1.y,
                           m10 * a0.z + m11 * a1.z, m10 * a0.w + m11 * a1.w};
            int so = qr * PV_APITCH + kc;
            split_store4(&sA[0][so], &sA[1][so], x0);
            split_store4(&sA[2][so], &sA[3][so], x1);
        }
        // stage V: [k][d] natural layout (trans happens in ldmatrix)
        {
            size_t go = (size_t)(k0 + vrow) * HD + vc8;
            int so = vrow * PV_VPITCH + vc8;
            *(uint4*)&sV[0][so]      = *(const uint4*)&V0h[go];
            *(uint4*)&sV[0][so + 64] = *(const uint4*)&V1h[go];
            *(uint4*)&sV[1][so]      = *(const uint4*)&V0l[go];
            *(uint4*)&sV[1][so + 64] = *(const uint4*)&V1l[go];
        }
        __syncthreads();
#pragma unroll
        for (int kk = 0; kk < 32; kk += 16) {
            uint32_t ah[4], al[4];
            uint32_t ro = (uint32_t)((wm * 16 + a_r) * PV_APITCH + kk + a_c8) * 2;
            ldsm_x4(ah, sAh + ro);
            ldsm_x4(al, sAl + ro);
            uint32_t bhf[4][4], blf[4][4];
#pragma unroll
            for (int t = 0; t < 4; t++) {
                uint32_t vo = (uint32_t)((kk + bt_r) * PV_VPITCH + wn * 64 + t * 16 + bt_c8) * 2;
                ldsm_x4_t(bhf[t], sVh + vo);
                ldsm_x4_t(blf[t], sVl + vo);
            }
#pragma unroll
            for (int nt = 0; nt < 8; nt++) {
                const uint32_t* bp  = &bhf[nt >> 1][(nt & 1) * 2];
                const uint32_t* blp = &blf[nt >> 1][(nt & 1) * 2];
                mma_bf16(acc[nt], ah, bp);
                mma_bf16(acc[nt], al, bp);
                mma_bf16(acc[nt], ah, blp);
            }
        }
        __syncthreads();
    }

    // epilogue: constant tail + DyT -> bf16 hi/lo
    const int bhh = wn ? bh1 : bh0;
    const float* suff = g_suffV + ((size_t)bhh * 17 + cidx) * HD;
    const float* csum = g_suffV + ((size_t)bhh * 17 + 0) * HD;
    const float* rc0 = g_rowconst + bh0 * S;
    const float* rc1 = g_rowconst + bh1 * S;
    const float ma = wn ? m10 : m00, mbx = wn ? m11 : m01;
    const float mb = mix_b[wn ? h1 : h0];
    const float alpha = dyt_alpha[0], ds = depth_scale[0];
    const int q0r = Q0 + wm * 16 + (lane >> 2);
    const float cm0 = ma * rc0[q0r] + mbx * rc1[q0r];
    const float cm1 = ma * rc0[q0r + 8] + mbx * rc1[q0r + 8];
    __nv_bfloat16* Oh = g_aoh + (size_t)b * S * E + h0 * HD;
    __nv_bfloat16* Ol = g_aol + (size_t)b * S * E + h0 * HD;

#pragma unroll
    for (int nt = 0; nt < 8; nt++) {
        int d = wn * 64 + nt * 8 + (lane & 3) * 2;
        int dl = d & 63;
        float sw0 = suff[dl], sw1 = suff[dl + 1];
        float cs0 = csum[dl], cs1 = csum[dl + 1];
        float w0 = dyt_w[dl], w1 = dyt_w[dl + 1];
        float bb0 = dyt_b[dl], bb1 = dyt_b[dl + 1];
#pragma unroll
        for (int half = 0; half < 2; half++) {
            int q = q0r + half * 8;
            float cm = half ? cm1 : cm0;
            float v0 = acc[nt][half * 2 + 0] + cm * sw0 + mb * cs0;
            float v1 = acc[nt][half * 2 + 1] + cm * sw1 + mb * cs1;
            v0 = (tanhf(alpha * v0) * w0 + bb0) * ds;
            v1 = (tanhf(alpha * v1) * w1 + bb1) * ds;
            __nv_bfloat16 h0v = __float2bfloat16(v0), h1v = __float2bfloat16(v1);
            *(__nv_bfloat162*)&Oh[(size_t)q * E + d] = __halves2bfloat162(h0v, h1v);
            *(__nv_bfloat162*)&Ol[(size_t)q * E + d] = __halves2bfloat162(
                __float2bfloat16(v0 - __bfloat162float(h0v)),
                __float2bfloat16(v1 - __bfloat162float(h1v)));
        }
    }
}

// ============================================================================
// Launch
// ============================================================================
extern "C" void kernel_launch(void* const* d_in, const int* in_sizes, int n_in,
                              void* d_out, int out_size)
{
    const float* Q   = (const float*)d_in[0];
    const float* K   = (const float*)d_in[1];
    const float* V   = (const float*)d_in[2];
    const float* Wq  = (const float*)d_in[3];
    const float* bq  = (const float*)d_in[4];
    const float* Wk  = (const float*)d_in[5];
    const float* bk  = (const float*)d_in[6];
    const float* Wv  = (const float*)d_in[7];
    const float* bv  = (const float*)d_in[8];
    const float* Wo  = (const float*)d_in[9];
    const float* bo  = (const float*)d_in[10];
    const float* kq_w = (const float*)d_in[11];
    const float* kq_b = (const float*)d_in[12];
    const float* mix_w = (const float*)d_in[13];
    const float* mix_b = (const float*)d_in[14];
    const float* dyt_alpha = (const float*)d_in[15];
    const float* dyt_w = (const float*)d_in[16];
    const float* dyt_b = (const float*)d_in[17];
    const float* depth_scale = (const float*)d_in[18];

    cudaFuncSetAttribute(gemm_qkv_tc, cudaFuncAttributeMaxDynamicSharedMemorySize, GEMM_SMEM);
    cudaFuncSetAttribute(gemm_out_tc, cudaFuncAttributeMaxDynamicSharedMemorySize, GEMM_SMEM);
    cudaFuncSetAttribute(logits_mma_kernel, cudaFuncAttributeMaxDynamicSharedMemorySize, LOG_SMEM);

    asplit_kernel<<<dim3(2048, 1, 3), 256>>>(Q, K, V);
    wsplit_kernel<<<dim3(32, 32, 4), dim3(32, 8)>>>(Wq, Wk, Wv, Wo);
    gemm_qkv_tc<<<dim3(8, 16, 3), 256, GEMM_SMEM>>>(bq, bk, bv);
    vchunk_kernel<<<dim3(BH, 16), 256>>>();
    vscan_kernel<<<BH, 64>>>();
    logits_mma_kernel<<<dim3(36, BH), 256, LOG_SMEM>>>();
    conv_softmax_kernel<<<dim3(S / QROWS, BH), 256>>>(kq_w, kq_b);
    pv_mma_kernel<<<dim3(1, S / 64, BH / 2), 256>>>(mix_w, mix_b, dyt_alpha, dyt_w, dyt_b, depth_scale);
    gemm_out_tc<<<dim3(8, 16), 256, GEMM_SMEM>>>(bo, (float*)d_out);
}